// round 9
// baseline (speedup 1.0000x reference)
#include <cuda_runtime.h>
#include <cuda_bf16.h>
#include <cuda_fp16.h>
#include <cstdint>
#include <cstddef>

#define NN  50000
#define EE  800000
#define DIN 128
#define HH  256
#define NBLK 49   // ceil(NN/1024)

// ---------------- static device scratch ----------------
__device__ __align__(16) __half g_hw[(size_t)NN * HH];     // GEMM output, dinv-scaled, fp16
__device__ __align__(16) float g_h1[(size_t)NN * HH];      // raw agg1 output
__device__ __align__(16) float g_h1n[(size_t)NN * HH];     // post-BN/LN h1 (residual source)
__device__ __align__(16) float g_h2[(size_t)NN * HH];      // raw agg2 output
__device__ __align__(16) float g_stats[1536];
__device__ __align__(16) float g_s0[DIN];
__device__ __align__(16) float g_t0[DIN];
__device__ __align__(16) float g_e[HH];
__device__ float g_dinv[NN];
__device__ int   g_deg[NN];
__device__ int   g_off[NN + 1];
__device__ int   g_cur[NN];
__device__ int   g_esrc[EE];
__device__ int   g_bsum[NBLK];
__device__ int   g_bsumx[NBLK];
__device__ __align__(16) __nv_bfloat16 g_w1h[HH * DIN];
__device__ __align__(16) __nv_bfloat16 g_w1l[HH * DIN];
__device__ __align__(16) __nv_bfloat16 g_w2h[HH * HH];
__device__ __align__(16) __nv_bfloat16 g_w2l[HH * HH];

// ---------------- helpers ----------------
__device__ __forceinline__ uint32_t smem_u32(const void* p) {
    uint32_t a;
    asm("{ .reg .u64 t; cvta.to.shared.u64 t, %1; cvt.u32.u64 %0, t; }" : "=r"(a) : "l"(p));
    return a;
}
__device__ __forceinline__ void ldm4(uint32_t* r, uint32_t addr) {
    asm volatile("ldmatrix.sync.aligned.m8n8.x4.shared.b16 {%0,%1,%2,%3}, [%4];"
                 : "=r"(r[0]), "=r"(r[1]), "=r"(r[2]), "=r"(r[3]) : "r"(addr));
}
__device__ __forceinline__ void mma16816(float* c, const uint32_t* a, const uint32_t* b) {
    asm volatile("mma.sync.aligned.m16n8k16.row.col.f32.bf16.bf16.f32 "
                 "{%0,%1,%2,%3}, {%4,%5,%6,%7}, {%8,%9}, {%0,%1,%2,%3};"
                 : "+f"(c[0]), "+f"(c[1]), "+f"(c[2]), "+f"(c[3])
                 : "r"(a[0]), "r"(a[1]), "r"(a[2]), "r"(a[3]), "r"(b[0]), "r"(b[1]));
}
__device__ __forceinline__ void cpa16(uint32_t dst, const void* src, uint32_t vld) {
    asm volatile("cp.async.cg.shared.global [%0], [%1], 16, %2;"
                 :: "r"(dst), "l"(src), "r"(vld) : "memory");
}
#define CP_COMMIT() asm volatile("cp.async.commit_group;" ::: "memory")

__device__ __forceinline__ void ld8(float* o, const float* p, int lane) {
    float4 a = ((const float4*)p)[lane];
    float4 b = ((const float4*)p)[32 + lane];
    o[0]=a.x; o[1]=a.y; o[2]=a.z; o[3]=a.w;
    o[4]=b.x; o[5]=b.y; o[6]=b.z; o[7]=b.w;
}
__device__ __forceinline__ void st8(float* p, int lane, const float* v) {
    ((float4*)p)[lane]      = make_float4(v[0], v[1], v[2], v[3]);
    ((float4*)p)[32 + lane] = make_float4(v[4], v[5], v[6], v[7]);
}
__device__ __forceinline__ void ldh8(float* o, const __half* p, int lane) {
    uint2 a = __ldg((const uint2*)p + lane);
    uint2 b = __ldg((const uint2*)p + 32 + lane);
    float2 f;
    f = __half22float2(*(__half2*)&a.x); o[0]=f.x; o[1]=f.y;
    f = __half22float2(*(__half2*)&a.y); o[2]=f.x; o[3]=f.y;
    f = __half22float2(*(__half2*)&b.x); o[4]=f.x; o[5]=f.y;
    f = __half22float2(*(__half2*)&b.y); o[6]=f.x; o[7]=f.y;
}
__device__ __forceinline__ void split_bf16(float v, __nv_bfloat16& h, __nv_bfloat16& l) {
    h = __float2bfloat16_rn(v);
    l = __float2bfloat16_rn(v - __bfloat162float(h));
}
__device__ __forceinline__ void acc_edge(float* acc, const __half* hw, int s, int lane) {
    const uint2* rp = (const uint2*)(hw + (size_t)s * HH);
    uint2 a = __ldg(rp + lane);
    uint2 b = __ldg(rp + 32 + lane);
    float2 f;
    f = __half22float2(*(__half2*)&a.x); acc[0] += f.x; acc[1] += f.y;
    f = __half22float2(*(__half2*)&a.y); acc[2] += f.x; acc[3] += f.y;
    f = __half22float2(*(__half2*)&b.x); acc[4] += f.x; acc[5] += f.y;
    f = __half22float2(*(__half2*)&b.y); acc[6] += f.x; acc[7] += f.y;
}

// ---------------- graph preprocessing ----------------
__global__ void k_zero_all() {
    int i = blockIdx.x * blockDim.x + threadIdx.x;
    if (i < 1536) g_stats[i] = 0.0f;
}
__global__ void k_zero_deg() {
    int i = blockIdx.x * blockDim.x + threadIdx.x;
    if (i < NN) g_deg[i] = 0;
}
__global__ void k_count(const int* __restrict__ dst) {
    int e = blockIdx.x * blockDim.x + threadIdx.x;
    if (e < EE) atomicAdd(&g_deg[dst[e]], 1);
}
__global__ void k_dinv() {
    int i = blockIdx.x * blockDim.x + threadIdx.x;
    if (i < NN) g_dinv[i] = rsqrtf((float)g_deg[i] + 1.0f);
}
__global__ void k_scan1() {
    __shared__ int wsum[32];
    int i = blockIdx.x * 1024 + threadIdx.x;
    int lane = threadIdx.x & 31, w = threadIdx.x >> 5;
    int v = (i < NN) ? g_deg[i] : 0;
    int inc = v;
    #pragma unroll
    for (int o = 1; o < 32; o <<= 1) {
        int t = __shfl_up_sync(0xffffffffu, inc, o);
        if (lane >= o) inc += t;
    }
    if (lane == 31) wsum[w] = inc;
    __syncthreads();
    if (w == 0) {
        int s = wsum[lane];
        int si = s;
        #pragma unroll
        for (int o = 1; o < 32; o <<= 1) {
            int t = __shfl_up_sync(0xffffffffu, si, o);
            if (lane >= o) si += t;
        }
        wsum[lane] = si - s;
    }
    __syncthreads();
    int excl = wsum[w] + inc - v;
    if (i < NN) g_off[i] = excl;
    if (threadIdx.x == 1023) g_bsum[blockIdx.x] = excl + v;
}
__global__ void k_scan2() {
    __shared__ int sh[2];
    int t = threadIdx.x, lane = t & 31, w = t >> 5;
    int v = (t < NBLK) ? g_bsum[t] : 0;
    int inc = v;
    #pragma unroll
    for (int o = 1; o < 32; o <<= 1) {
        int x = __shfl_up_sync(0xffffffffu, inc, o);
        if (lane >= o) inc += x;
    }
    if (lane == 31) sh[w] = inc;
    __syncthreads();
    int add = (w == 1) ? sh[0] : 0;
    int excl = inc - v + add;
    if (t < NBLK) g_bsumx[t] = excl;
    if (t == NBLK - 1) g_off[NN] = excl + v;
}
__global__ void k_scan3() {
    int i = blockIdx.x * blockDim.x + threadIdx.x;
    if (i < NN) {
        int o = g_off[i] + g_bsumx[i >> 10];
        g_off[i] = o;
        g_cur[i] = o;
    }
}
__global__ void k_scatter(const int* __restrict__ src, const int* __restrict__ dst) {
    int e = blockIdx.x * blockDim.x + threadIdx.x;
    if (e >= EE) return;
    int p = atomicAdd(&g_cur[dst[e]], 1);
    g_esrc[p] = src[e];
}

// ---------------- weight transpose + bf16 split ----------------
template <int K>
__global__ void k_prep_w(const float* __restrict__ W,
                         __nv_bfloat16* __restrict__ oh, __nv_bfloat16* __restrict__ ol) {
    int i = blockIdx.x * blockDim.x + threadIdx.x;
    if (i >= HH * K) return;
    int n = i & (HH - 1), k = i >> 8;
    float v = W[k * HH + n];
    __nv_bfloat16 h, l;
    split_bf16(v, h, l);
    oh[n * K + k] = h;
    ol[n * K + k] = l;
}

// ---------------- BN0 fold ----------------
__global__ void k_colstats0(const float* __restrict__ A,
                            const float* __restrict__ fs, const float* __restrict__ fb) {
    int c = threadIdx.x;
    float scale = fs[c], bias = fb[c];
    float s = 0.0f, q = 0.0f;
    for (int r = blockIdx.x; r < NN; r += gridDim.x) {
        float v = A[(size_t)r * DIN + c] * scale + bias;
        s += v; q += v * v;
    }
    atomicAdd(&g_stats[c], s);
    atomicAdd(&g_stats[256 + c], q);
}
__global__ void k_fold(const float* __restrict__ fs, const float* __restrict__ fb,
                       const float* __restrict__ g,  const float* __restrict__ b) {
    int c = threadIdx.x;
    float mu  = g_stats[c] * (1.0f / NN);
    float var = g_stats[256 + c] * (1.0f / NN) - mu * mu;
    float a   = g[c] * rsqrtf(var + 1e-5f);
    g_s0[c] = fs[c] * a;
    g_t0[c] = (fb[c] - mu) * a + b[c];
}
__global__ void k_e(const float* __restrict__ W1) {
    int n = threadIdx.x;
    float e = 0.0f;
    #pragma unroll 8
    for (int k = 0; k < DIN; k++) e += g_t0[k] * W1[k * HH + n];
    g_e[n] = e;
}

// ---------------- GEMM1: single-chunk K=128, fp32 x with folded BN0 ----------------
__global__ __launch_bounds__(256)
void k_gemm1(const float* __restrict__ X,
             const __nv_bfloat16* __restrict__ Bh, const __nv_bfloat16* __restrict__ Bl,
             __half* __restrict__ C) {
    constexpr int LDS = 136;
    extern __shared__ __nv_bfloat16 sm[];
    const uint32_t A_HI = 0, A_LO = 128u * LDS * 2, B_HI = 2u * 128 * LDS * 2, B_LO = 3u * 128 * LDS * 2;
    char* smp = (char*)sm;

    const int tid = threadIdx.x, lane = tid & 31, wid = tid >> 5;
    const int wm = wid >> 1, wn = wid & 1;
    const int row0 = blockIdx.y * 128;
    const int n0   = blockIdx.x * 128;
    const uint32_t smb = smem_u32(sm);

    #pragma unroll
    for (int it = 0; it < 8; it++) {
        int idx = tid + it * 256;
        int r = idx >> 4, q = idx & 15;
        size_t go = (size_t)(n0 + r) * DIN + q * 8;
        uint32_t so = (uint32_t)(r * LDS + q * 8) * 2;
        cpa16(smb + B_HI + so, Bh + go, 16u);
        cpa16(smb + B_LO + so, Bl + go, 16u);
    }
    CP_COMMIT();

    #pragma unroll
    for (int it = 0; it < 16; it++) {
        int idx = tid + it * 256;
        int r = idx >> 5, q = idx & 31;
        int gr = row0 + r;
        float4 v = make_float4(0.f, 0.f, 0.f, 0.f);
        if (gr < NN) v = ((const float4*)X)[(size_t)gr * 32 + q];
        float4 s4 = ((const float4*)g_s0)[q];
        v.x *= s4.x; v.y *= s4.y; v.z *= s4.z; v.w *= s4.w;
        __nv_bfloat16 h[4], l[4];
        split_bf16(v.x, h[0], l[0]); split_bf16(v.y, h[1], l[1]);
        split_bf16(v.z, h[2], l[2]); split_bf16(v.w, h[3], l[3]);
        uint32_t off = (uint32_t)(r * LDS + q * 4) * 2;
        *(uint2*)(smp + A_HI + off) = *(uint2*)h;
        *(uint2*)(smp + A_LO + off) = *(uint2*)l;
    }
    asm volatile("cp.async.wait_group 0;" ::: "memory");
    __syncthreads();

    float c[2][8][4] = {};
    const int a_row = wm * 32 + (lane & 15);
    const int a_kof = (lane >> 4) * 8;
    const int b_row = wn * 64 + ((lane >> 4) << 3) + (lane & 7);
    const int b_kof = ((lane >> 3) & 1) * 8;

    #pragma unroll
    for (int k16 = 0; k16 < 8; k16++) {
        uint32_t ah[2][4], al[2][4];
        #pragma unroll
        for (int mt = 0; mt < 2; mt++) {
            uint32_t ro = ((a_row + mt * 16) * LDS + k16 * 16 + a_kof) * 2;
            ldm4(ah[mt], smb + A_HI + ro);
            ldm4(al[mt], smb + A_LO + ro);
        }
        uint32_t bh[8][2], bl[8][2];
        #pragma unroll
        for (int p = 0; p < 4; p++) {
            uint32_t ro = ((b_row + p * 16) * LDS + k16 * 16 + b_kof) * 2;
            uint32_t r4[4];
            ldm4(r4, smb + B_HI + ro);
            bh[2*p][0]=r4[0]; bh[2*p][1]=r4[1]; bh[2*p+1][0]=r4[2]; bh[2*p+1][1]=r4[3];
            ldm4(r4, smb + B_LO + ro);
            bl[2*p][0]=r4[0]; bl[2*p][1]=r4[1]; bl[2*p+1][0]=r4[2]; bl[2*p+1][1]=r4[3];
        }
        #pragma unroll
        for (int mt = 0; mt < 2; mt++)
            #pragma unroll
            for (int nt = 0; nt < 8; nt++) {
                mma16816(c[mt][nt], ah[mt], bh[nt]);
                mma16816(c[mt][nt], al[mt], bh[nt]);
                mma16816(c[mt][nt], ah[mt], bl[nt]);
            }
    }

    const int g = lane >> 2, t = lane & 3;
    #pragma unroll
    for (int mt = 0; mt < 2; mt++) {
        int rbase = row0 + wm * 32 + mt * 16;
        int r1w = rbase + g, r2w = rbase + g + 8;
        float s1 = (r1w < NN) ? g_dinv[r1w] : 0.0f;
        float s2 = (r2w < NN) ? g_dinv[r2w] : 0.0f;
        #pragma unroll
        for (int nt = 0; nt < 8; nt++) {
            int col = n0 + wn * 64 + nt * 8 + 2 * t;
            float2 ev = *(const float2*)(g_e + col);
            if (r1w < NN)
                *(__half2*)(C + (size_t)r1w * HH + col) =
                    __floats2half2_rn((c[mt][nt][0] + ev.x) * s1, (c[mt][nt][1] + ev.y) * s1);
            if (r2w < NN)
                *(__half2*)(C + (size_t)r2w * HH + col) =
                    __floats2half2_rn((c[mt][nt][2] + ev.x) * s2, (c[mt][nt][3] + ev.y) * s2);
        }
    }
}

// ---------------- GEMM2 fused: BN->LN on raw h1 in A-load, then K=256 GEMM ----------
// A resident in smem (bf16 hi/lo, 128x256), B 2-stage cp.async.
// Also writes post-LN h1 (residual source) from blockIdx.x==0 CTAs only.
__global__ __launch_bounds__(256)
void k_gemm2f(const float* __restrict__ H1raw, const float* __restrict__ stats,
              const float* __restrict__ bng, const float* __restrict__ bnb,
              const float* __restrict__ lng, const float* __restrict__ lnb,
              float* __restrict__ H1n,
              const __nv_bfloat16* __restrict__ Bh, const __nv_bfloat16* __restrict__ Bl,
              __half* __restrict__ C) {
    constexpr int K = HH, BK = 64, NCH = K / BK;
    constexpr int LDSA = 264;                         // halves per A row (256 + 8 pad)
    constexpr int LDSB = 72;
    constexpr uint32_t A_SZ = 128u * LDSA * 2;        // 67584 per split
    constexpr uint32_t B_OFF = 2u * A_SZ;             // 135168
    constexpr uint32_t B_STG = 2u * 128 * LDSB * 2;   // 36864 per stage (hi+lo)
    extern __shared__ __nv_bfloat16 sm[];
    char* smp = (char*)sm;

    const int tid = threadIdx.x, lane = tid & 31, wid = tid >> 5;
    const int wm = wid >> 1, wn = wid & 1;
    const int row0 = blockIdx.y * 128;
    const int n0   = blockIdx.x * 128;
    const uint32_t smb = smem_u32(sm);

    auto load_B = [&](int ch, int buf) {
        const uint32_t sb = smb + B_OFF + (uint32_t)buf * B_STG;
        #pragma unroll
        for (int it = 0; it < 4; it++) {
            int idx = tid + it * 256;
            int r = idx >> 3, q = idx & 7;
            size_t go = (size_t)(n0 + r) * K + ch * BK + q * 8;
            uint32_t so = (uint32_t)(r * LDSB + q * 8) * 2;
            cpa16(sb + so, Bh + go, 16u);
            cpa16(sb + 128 * LDSB * 2 + so, Bl + go, 16u);
        }
        CP_COMMIT();
    };

    load_B(0, 0);
    load_B(1, 1);

    // ---- fused BN -> LN on this CTA's 128 A-rows (warp per row, 16 iters) ----
    {
        float sb[8], qb[8], bg[8], bb[8], lg[8], lb[8];
        ld8(sb, stats, lane);
        ld8(qb, stats + 256, lane);
        ld8(bg, bng, lane);
        ld8(bb, bnb, lane);
        ld8(lg, lng, lane);
        ld8(lb, lnb, lane);
        float bnsc[8], bnsh[8];
        #pragma unroll
        for (int i = 0; i < 8; i++) {
            float mu  = sb[i] * (1.0f / NN);
            float var = qb[i] * (1.0f / NN) - mu * mu;
            bnsc[i] = bg[i] * rsqrtf(var + 1e-5f);
            bnsh[i] = bb[i] - mu * bnsc[i];
        }
        #pragma unroll
        for (int it = 0; it < 16; it++) {
            int lr = wid + it * 8;
            int gr = row0 + lr;
            float v[8] = {0.f, 0.f, 0.f, 0.f, 0.f, 0.f, 0.f, 0.f};
            if (gr < NN) {
                ld8(v, H1raw + (size_t)gr * HH, lane);
                #pragma unroll
                for (int i = 0; i < 8; i++) v[i] = v[i] * bnsc[i] + bnsh[i];
                float sum = 0.f;
                #pragma unroll
                for (int i = 0; i < 8; i++) sum += v[i];
                #pragma unroll
                for (int o = 16; o; o >>= 1) sum += __shfl_xor_sync(0xffffffffu, sum, o);
                float mu = sum * (1.0f / HH);
                float ss = 0.f;
                #pragma unroll
                for (int i = 0; i < 8; i++) { float dd = v[i] - mu; ss += dd * dd; }
                #pragma unroll
                for (int o = 16; o; o >>= 1) ss += __shfl_xor_sync(0xffffffffu, ss, o);
                float rs = rsqrtf(ss * (1.0f / HH) + 1e-5f);
                #pragma unroll
                for (int i = 0; i < 8; i++) v[i] = lg[i] * (v[i] - mu) * rs + lb[i];
                if (blockIdx.x == 0) st8(H1n + (size_t)gr * HH, lane, v);
            }
            // split and store to smem A (cols: lane*4 + i  and  128 + lane*4 + i)
            __nv_bfloat16 h[4], l[4];
            #pragma unroll
            for (int i = 0; i < 4; i++) split_bf16(v[i], h[i], l[i]);
            uint32_t off = (uint32_t)(lr * LDSA + lane * 4) * 2;
            *(uint2*)(smp + off) = *(uint2*)h;
            *(uint2*)(smp + A_SZ + off) = *(uint2*)l;
            #pragma unroll
            for (int i = 0; i < 4; i++) split_bf16(v[4 + i], h[i], l[i]);
            off = (uint32_t)(lr * LDSA + 128 + lane * 4) * 2;
            *(uint2*)(smp + off) = *(uint2*)h;
            *(uint2*)(smp + A_SZ + off) = *(uint2*)l;
        }
    }

    float c[2][8][4] = {};
    const int a_row = wm * 32 + (lane & 15);
    const int a_kof = (lane >> 4) * 8;
    const int b_row = wn * 64 + ((lane >> 4) << 3) + (lane & 7);
    const int b_kof = ((lane >> 3) & 1) * 8;

    #pragma unroll
    for (int ch = 0; ch < NCH; ch++) {
        if (ch + 2 < NCH) {
            asm volatile("cp.async.wait_group 1;" ::: "memory");
        } else {
            asm volatile("cp.async.wait_group 0;" ::: "memory");
        }
        __syncthreads();

        const uint32_t bbase = smb + B_OFF + (uint32_t)(ch & 1) * B_STG;
        #pragma unroll
        for (int k16 = 0; k16 < BK / 16; k16++) {
            uint32_t ah[2][4], al[2][4];
            #pragma unroll
            for (int mt = 0; mt < 2; mt++) {
                uint32_t ro = ((a_row + mt * 16) * LDSA + ch * BK + k16 * 16 + a_kof) * 2;
                ldm4(ah[mt], smb + ro);
                ldm4(al[mt], smb + A_SZ + ro);
            }
            uint32_t bh[8][2], bl[8][2];
            #pragma unroll
            for (int p = 0; p < 4; p++) {
                uint32_t ro = ((b_row + p * 16) * LDSB + k16 * 16 + b_kof) * 2;
                uint32_t r4[4];
                ldm4(r4, bbase + ro);
                bh[2*p][0]=r4[0]; bh[2*p][1]=r4[1]; bh[2*p+1][0]=r4[2]; bh[2*p+1][1]=r4[3];
                ldm4(r4, bbase + 128 * LDSB * 2 + ro);
                bl[2*p][0]=r4[0]; bl[2*p][1]=r4[1]; bl[2*p+1][0]=r4[2]; bl[2*p+1][1]=r4[3];
            }
            #pragma unroll
            for (int mt = 0; mt < 2; mt++)
                #pragma unroll
                for (int nt = 0; nt < 8; nt++) {
                    mma16816(c[mt][nt], ah[mt], bh[nt]);
                    mma16816(c[mt][nt], al[mt], bh[nt]);
                    mma16816(c[mt][nt], ah[mt], bl[nt]);
                }
        }
        __syncthreads();
        if (ch + 2 < NCH) load_B(ch + 2, ch & 1);
    }

    const int g = lane >> 2, t = lane & 3;
    #pragma unroll
    for (int mt = 0; mt < 2; mt++) {
        int rbase = row0 + wm * 32 + mt * 16;
        int r1w = rbase + g, r2w = rbase + g + 8;
        float s1 = (r1w < NN) ? g_dinv[r1w] : 0.0f;
        float s2 = (r2w < NN) ? g_dinv[r2w] : 0.0f;
        #pragma unroll
        for (int nt = 0; nt < 8; nt++) {
            int col = n0 + wn * 64 + nt * 8 + 2 * t;
            if (r1w < NN)
                *(__half2*)(C + (size_t)r1w * HH + col) =
                    __floats2half2_rn(c[mt][nt][0] * s1, c[mt][nt][1] * s1);
            if (r2w < NN)
                *(__half2*)(C + (size_t)r2w * HH + col) =
                    __floats2half2_rn(c[mt][nt][2] * s2, c[mt][nt][3] * s2);
        }
    }
}

// ---------------- GCN aggregation (coalesced idx + shfl, 4x unrolled) ----------
__global__ __launch_bounds__(256)
void k_aggregate(const __half* __restrict__ hw, const float* __restrict__ bias,
                 float* __restrict__ out, float* __restrict__ stats) {
    __shared__ float red[8][256];
    int d    = (blockIdx.x * blockDim.x + threadIdx.x) >> 5;
    int lane = threadIdx.x & 31;
    int wid  = threadIdx.x >> 5;

    float acc[8] = {};
    const int beg = g_off[d], end = g_off[d + 1];

    int p0 = beg;
    while (p0 < end) {
        int cnt = end - p0;
        if (cnt > 32) cnt = 32;
        int idxv = (lane < cnt) ? g_esrc[p0 + lane] : 0;
        int j = 0;
        for (; j + 4 <= cnt; j += 4) {
            int s0 = __shfl_sync(0xffffffffu, idxv, j);
            int s1 = __shfl_sync(0xffffffffu, idxv, j + 1);
            int s2 = __shfl_sync(0xffffffffu, idxv, j + 2);
            int s3 = __shfl_sync(0xffffffffu, idxv, j + 3);
            acc_edge(acc, hw, s0, lane);
            acc_edge(acc, hw, s1, lane);
            acc_edge(acc, hw, s2, lane);
            acc_edge(acc, hw, s3, lane);
        }
        for (; j < cnt; j++) {
            int s0 = __shfl_sync(0xffffffffu, idxv, j);
            acc_edge(acc, hw, s0, lane);
        }
        p0 += cnt;
    }

    float di = g_dinv[d];
    float sv[8], bv[8], r[8];
    ldh8(sv, hw + (size_t)d * HH, lane);
    ld8(bv, bias, lane);
    #pragma unroll
    for (int i = 0; i < 8; i++)
        r[i] = fmaxf(di * (acc[i] + sv[i]) + bv[i], 0.0f);
    st8(out + (size_t)d * HH, lane, r);

    st8(&red[wid][0], lane, r);
    __syncthreads();
    int cidx = threadIdx.x;
    float s = 0.f, q = 0.f;
    #pragma unroll
    for (int w = 0; w < 8; w++) {
        float v = red[w][cidx];
        s += v; q += v * v;
    }
    atomicAdd(&stats[cidx], s);
    atomicAdd(&stats[256 + cidx], q);
}

// ---------------- final fused BN -> LN -> +residual -> out-proj ----------------
__global__ __launch_bounds__(256)
void k_bn_ln_out(const float* __restrict__ t, const float* __restrict__ stats,
                 const float* __restrict__ bng, const float* __restrict__ bnb,
                 const float* __restrict__ lng, const float* __restrict__ lnb,
                 const float* __restrict__ res,
                 const float* __restrict__ Wout, const float* __restrict__ bout,
                 float* __restrict__ out) {
    int row  = (blockIdx.x * blockDim.x + threadIdx.x) >> 5;
    int lane = threadIdx.x & 31;
    if (row >= NN) return;

    float v[8], s[8], q[8], g[8], b[8];
    ld8(v, t + (size_t)row * HH, lane);
    ld8(s, stats, lane);
    ld8(q, stats + 256, lane);
    ld8(g, bng, lane);
    ld8(b, bnb, lane);

    #pragma unroll
    for (int i = 0; i < 8; i++) {
        float mu  = s[i] * (1.0f / NN);
        float var = q[i] * (1.0f / NN) - mu * mu;
        v[i] = g[i] * (v[i] - mu) * rsqrtf(var + 1e-5f) + b[i];
    }

    float sum = 0.f;
    #pragma unroll
    for (int i = 0; i < 8; i++) sum += v[i];
    #pragma unroll
    for (int o = 16; o; o >>= 1) sum += __shfl_xor_sync(0xffffffffu, sum, o);
    float mu = sum * (1.0f / HH);

    float ss = 0.f;
    #pragma unroll
    for (int i = 0; i < 8; i++) { float dd = v[i] - mu; ss += dd * dd; }
    #pragma unroll
    for (int o = 16; o; o >>= 1) ss += __shfl_xor_sync(0xffffffffu, ss, o);
    float rs = rsqrtf(ss * (1.0f / HH) + 1e-5f);

    ld8(g, lng, lane);
    ld8(b, lnb, lane);
    float r[8];
    ld8(r, res + (size_t)row * HH, lane);
    #pragma unroll
    for (int i = 0; i < 8; i++) v[i] = g[i] * (v[i] - mu) * rs + b[i] + r[i];

    const float4* W4 = (const float4*)Wout;
    float4 wA = W4[2 * lane],      wB = W4[2 * lane + 1];
    float4 wC = W4[64 + 2 * lane], wD = W4[65 + 2 * lane];
    float a0 = v[0]*wA.x + v[1]*wA.z + v[2]*wB.x + v[3]*wB.z
             + v[4]*wC.x + v[5]*wC.z + v[6]*wD.x + v[7]*wD.z;
    float a1 = v[0]*wA.y + v[1]*wA.w + v[2]*wB.y + v[3]*wB.w
             + v[4]*wC.y + v[5]*wC.w + v[6]*wD.y + v[7]*wD.w;
    #pragma unroll
    for (int o = 16; o; o >>= 1) {
        a0 += __shfl_xor_sync(0xffffffffu, a0, o);
        a1 += __shfl_xor_sync(0xffffffffu, a1, o);
    }
    if (lane == 0) {
        out[2 * row]     = a0 + bout[0];
        out[2 * row + 1] = a1 + bout[1];
    }
}

// ---------------- streams + events ----------------
static cudaStream_t g_s2, g_s3;
static cudaEvent_t  g_evF, g_evZ, g_evD, g_evJ, g_evW;
namespace {
struct _HxInit {
    _HxInit() {
        cudaStreamCreateWithFlags(&g_s2, cudaStreamNonBlocking);
        cudaStreamCreateWithFlags(&g_s3, cudaStreamNonBlocking);
        cudaEventCreateWithFlags(&g_evF, cudaEventDisableTiming);
        cudaEventCreateWithFlags(&g_evZ, cudaEventDisableTiming);
        cudaEventCreateWithFlags(&g_evD, cudaEventDisableTiming);
        cudaEventCreateWithFlags(&g_evJ, cudaEventDisableTiming);
        cudaEventCreateWithFlags(&g_evW, cudaEventDisableTiming);
    }
};
static _HxInit _hx_init;
}

// ---------------- launch ----------------
extern "C" void kernel_launch(void* const* d_in, const int* in_sizes, int n_in,
                              void* d_out, int out_size) {
    const float* x    = (const float*)d_in[0];
    const int*   ei   = (const int*)  d_in[1];
    const float* fs   = (const float*)d_in[2];
    const float* fb   = (const float*)d_in[3];
    const float* bn0g = (const float*)d_in[4];
    const float* bn0b = (const float*)d_in[5];
    const float* W1   = (const float*)d_in[6];
    const float* b1   = (const float*)d_in[7];
    const float* bn1g = (const float*)d_in[8];
    const float* bn1b = (const float*)d_in[9];
    const float* ln1g = (const float*)d_in[10];
    const float* ln1b = (const float*)d_in[11];
    const float* W2   = (const float*)d_in[12];
    const float* b2   = (const float*)d_in[13];
    const float* bn2g = (const float*)d_in[14];
    const float* bn2b = (const float*)d_in[15];
    const float* ln2g = (const float*)d_in[16];
    const float* ln2b = (const float*)d_in[17];
    const float* Wout = (const float*)d_in[18];
    const float* bout = (const float*)d_in[19];
    float* out = (float*)d_out;

    const int* srcp = ei;
    const int* dstp = ei + EE;

    __half* p_hw;
    float *p_h1, *p_h1n, *p_h2, *p_stats;
    cudaGetSymbolAddress((void**)&p_hw, g_hw);
    cudaGetSymbolAddress((void**)&p_h1, g_h1);
    cudaGetSymbolAddress((void**)&p_h1n, g_h1n);
    cudaGetSymbolAddress((void**)&p_h2, g_h2);
    cudaGetSymbolAddress((void**)&p_stats, g_stats);
    __nv_bfloat16 *p_w1h, *p_w1l, *p_w2h, *p_w2l;
    cudaGetSymbolAddress((void**)&p_w1h, g_w1h);
    cudaGetSymbolAddress((void**)&p_w1l, g_w1l);
    cudaGetSymbolAddress((void**)&p_w2h, g_w2h);
    cudaGetSymbolAddress((void**)&p_w2l, g_w2l);

    const int G1_SMEM = 4 * 128 * 136 * 2;                    // 139264
    const int G2_SMEM = 2 * 128 * 264 * 2 + 2 * 2 * 128 * 72 * 2;  // 135168 + 73728 = 208896
    cudaFuncSetAttribute(k_gemm1,  cudaFuncAttributeMaxDynamicSharedMemorySize, G1_SMEM);
    cudaFuncSetAttribute(k_gemm2f, cudaFuncAttributeMaxDynamicSharedMemorySize, G2_SMEM);

    const int WARP_GRID = (NN * 32 + 255) / 256;  // 6250
    const dim3 MGRID(2, (NN + 127) / 128);

    // ---- fork ----
    cudaEventRecord(g_evF, 0);
    cudaStreamWaitEvent(g_s2, g_evF, 0);
    cudaStreamWaitEvent(g_s3, g_evF, 0);

    // side stream 2: stats zero + graph preprocessing
    k_zero_all<<<6, 256, 0, g_s2>>>();
    cudaEventRecord(g_evZ, g_s2);
    k_zero_deg<<<(NN + 255) / 256, 256, 0, g_s2>>>();
    k_count<<<(EE + 255) / 256, 256, 0, g_s2>>>(dstp);
    k_dinv<<<(NN + 255) / 256, 256, 0, g_s2>>>();
    cudaEventRecord(g_evD, g_s2);
    k_scan1<<<NBLK, 1024, 0, g_s2>>>();
    k_scan2<<<1, 64, 0, g_s2>>>();
    k_scan3<<<(NN + 1023) / 1024, 1024, 0, g_s2>>>();
    k_scatter<<<(EE + 255) / 256, 256, 0, g_s2>>>(srcp, dstp);
    cudaEventRecord(g_evJ, g_s2);

    // side stream 3: weight prep
    k_prep_w<DIN><<<(HH * DIN + 255) / 256, 256, 0, g_s3>>>(W1, p_w1h, p_w1l);
    k_prep_w<HH><<<(HH * HH + 255) / 256, 256, 0, g_s3>>>(W2, p_w2h, p_w2l);
    cudaEventRecord(g_evW, g_s3);

    // ---- main stream ----
    cudaStreamWaitEvent(0, g_evZ, 0);
    k_colstats0<<<1024, DIN>>>(x, fs, fb);
    k_fold<<<1, DIN>>>(fs, fb, bn0g, bn0b);
    k_e<<<1, HH>>>(W1);

    // layer 1 (BN0 folded into GEMM1)
    cudaStreamWaitEvent(0, g_evD, 0);
    cudaStreamWaitEvent(0, g_evW, 0);
    k_gemm1<<<MGRID, 256, G1_SMEM>>>(x, p_w1h, p_w1l, p_hw);
    cudaStreamWaitEvent(0, g_evJ, 0);
    k_aggregate<<<WARP_GRID, 256>>>(p_hw, b1, p_h1, p_stats + 512);

    // layer 2: BN1->LN1 fused into GEMM2's A-load; residual written to h1n
    k_gemm2f<<<MGRID, 256, G2_SMEM>>>(p_h1, p_stats + 512,
                                      bn1g, bn1b, ln1g, ln1b,
                                      p_h1n, p_w2h, p_w2l, p_hw);
    k_aggregate<<<WARP_GRID, 256>>>(p_hw, b2, p_h2, p_stats + 1024);
    k_bn_ln_out<<<WARP_GRID, 256>>>(p_h2, p_stats + 1024,
                                    bn2g, bn2b, ln2g, ln2b,
                                    p_h1n, Wout, bout, out);
}

// round 10
// speedup vs baseline: 1.1427x; 1.1427x over previous
#include <cuda_runtime.h>
#include <cuda_bf16.h>
#include <cuda_fp16.h>
#include <cstdint>
#include <cstddef>

#define NN  50000
#define EE  800000
#define DIN 128
#define HH  256
#define NBLK 49   // ceil(NN/1024)

// ---------------- static device scratch ----------------
__device__ __align__(16) __half g_hw[(size_t)NN * HH];     // GEMM output, dinv-scaled, fp16
__device__ __align__(16) float g_h1[(size_t)NN * HH];      // raw agg1 output
__device__ __align__(16) float g_h2[(size_t)NN * HH];      // raw agg2 output
__device__ __align__(16) float g_stats[1536];
__device__ __align__(16) float g_s0[DIN];
__device__ __align__(16) float g_t0[DIN];
__device__ __align__(16) float g_e[HH];
__device__ float g_dinv[NN];
__device__ int   g_deg[NN];
__device__ int   g_off[NN + 1];
__device__ int   g_cur[NN];
__device__ int   g_esrc[EE];
__device__ int   g_bsum[NBLK];
__device__ int   g_bsumx[NBLK];
// bf16 split of post-LN h1 — GEMM2 A operand AND residual source
__device__ __align__(16) __nv_bfloat16 g_a2h[(size_t)NN * HH];
__device__ __align__(16) __nv_bfloat16 g_a2l[(size_t)NN * HH];
__device__ __align__(16) __nv_bfloat16 g_w1h[HH * DIN];
__device__ __align__(16) __nv_bfloat16 g_w1l[HH * DIN];
__device__ __align__(16) __nv_bfloat16 g_w2h[HH * HH];
__device__ __align__(16) __nv_bfloat16 g_w2l[HH * HH];

// ---------------- helpers ----------------
__device__ __forceinline__ uint32_t smem_u32(const void* p) {
    uint32_t a;
    asm("{ .reg .u64 t; cvta.to.shared.u64 t, %1; cvt.u32.u64 %0, t; }" : "=r"(a) : "l"(p));
    return a;
}
__device__ __forceinline__ void ldm4(uint32_t* r, uint32_t addr) {
    asm volatile("ldmatrix.sync.aligned.m8n8.x4.shared.b16 {%0,%1,%2,%3}, [%4];"
                 : "=r"(r[0]), "=r"(r[1]), "=r"(r[2]), "=r"(r[3]) : "r"(addr));
}
__device__ __forceinline__ void mma16816(float* c, const uint32_t* a, const uint32_t* b) {
    asm volatile("mma.sync.aligned.m16n8k16.row.col.f32.bf16.bf16.f32 "
                 "{%0,%1,%2,%3}, {%4,%5,%6,%7}, {%8,%9}, {%0,%1,%2,%3};"
                 : "+f"(c[0]), "+f"(c[1]), "+f"(c[2]), "+f"(c[3])
                 : "r"(a[0]), "r"(a[1]), "r"(a[2]), "r"(a[3]), "r"(b[0]), "r"(b[1]));
}
__device__ __forceinline__ void cpa16(uint32_t dst, const void* src, uint32_t vld) {
    asm volatile("cp.async.cg.shared.global [%0], [%1], 16, %2;"
                 :: "r"(dst), "l"(src), "r"(vld) : "memory");
}
#define CP_COMMIT() asm volatile("cp.async.commit_group;" ::: "memory")

__device__ __forceinline__ void ld8(float* o, const float* p, int lane) {
    float4 a = ((const float4*)p)[lane];
    float4 b = ((const float4*)p)[32 + lane];
    o[0]=a.x; o[1]=a.y; o[2]=a.z; o[3]=a.w;
    o[4]=b.x; o[5]=b.y; o[6]=b.z; o[7]=b.w;
}
__device__ __forceinline__ void st8(float* p, int lane, const float* v) {
    ((float4*)p)[lane]      = make_float4(v[0], v[1], v[2], v[3]);
    ((float4*)p)[32 + lane] = make_float4(v[4], v[5], v[6], v[7]);
}
__device__ __forceinline__ void ldh8(float* o, const __half* p, int lane) {
    uint2 a = __ldg((const uint2*)p + lane);
    uint2 b = __ldg((const uint2*)p + 32 + lane);
    float2 f;
    f = __half22float2(*(__half2*)&a.x); o[0]=f.x; o[1]=f.y;
    f = __half22float2(*(__half2*)&a.y); o[2]=f.x; o[3]=f.y;
    f = __half22float2(*(__half2*)&b.x); o[4]=f.x; o[5]=f.y;
    f = __half22float2(*(__half2*)&b.y); o[6]=f.x; o[7]=f.y;
}
// load 8 floats reconstructed from a bf16 hi/lo split pair
__device__ __forceinline__ void ldsplit8(float* o, const __nv_bfloat16* ph,
                                         const __nv_bfloat16* pl, int lane) {
    uint2 hA = __ldg((const uint2*)ph + lane);
    uint2 hB = __ldg((const uint2*)ph + 32 + lane);
    uint2 lA = __ldg((const uint2*)pl + lane);
    uint2 lB = __ldg((const uint2*)pl + 32 + lane);
    const __nv_bfloat16* h = (const __nv_bfloat16*)&hA;
    const __nv_bfloat16* l = (const __nv_bfloat16*)&lA;
    #pragma unroll
    for (int i = 0; i < 4; i++) o[i] = __bfloat162float(h[i]) + __bfloat162float(l[i]);
    h = (const __nv_bfloat16*)&hB;
    l = (const __nv_bfloat16*)&lB;
    #pragma unroll
    for (int i = 0; i < 4; i++) o[4 + i] = __bfloat162float(h[i]) + __bfloat162float(l[i]);
}
__device__ __forceinline__ void split_bf16(float v, __nv_bfloat16& h, __nv_bfloat16& l) {
    h = __float2bfloat16_rn(v);
    l = __float2bfloat16_rn(v - __bfloat162float(h));
}
__device__ __forceinline__ void acc_edge(float* acc, const __half* hw, int s, int lane) {
    const uint2* rp = (const uint2*)(hw + (size_t)s * HH);
    uint2 a = __ldg(rp + lane);
    uint2 b = __ldg(rp + 32 + lane);
    float2 f;
    f = __half22float2(*(__half2*)&a.x); acc[0] += f.x; acc[1] += f.y;
    f = __half22float2(*(__half2*)&a.y); acc[2] += f.x; acc[3] += f.y;
    f = __half22float2(*(__half2*)&b.x); acc[4] += f.x; acc[5] += f.y;
    f = __half22float2(*(__half2*)&b.y); acc[6] += f.x; acc[7] += f.y;
}

// ---------------- graph preprocessing ----------------
__global__ void k_zero_all() {
    int i = blockIdx.x * blockDim.x + threadIdx.x;
    if (i < 1536) g_stats[i] = 0.0f;
}
__global__ void k_zero_deg() {
    int i = blockIdx.x * blockDim.x + threadIdx.x;
    if (i < NN) g_deg[i] = 0;
}
__global__ void k_count(const int* __restrict__ dst) {
    int e = blockIdx.x * blockDim.x + threadIdx.x;
    if (e < EE) atomicAdd(&g_deg[dst[e]], 1);
}
__global__ void k_dinv() {
    int i = blockIdx.x * blockDim.x + threadIdx.x;
    if (i < NN) g_dinv[i] = rsqrtf((float)g_deg[i] + 1.0f);
}
__global__ void k_scan1() {
    __shared__ int wsum[32];
    int i = blockIdx.x * 1024 + threadIdx.x;
    int lane = threadIdx.x & 31, w = threadIdx.x >> 5;
    int v = (i < NN) ? g_deg[i] : 0;
    int inc = v;
    #pragma unroll
    for (int o = 1; o < 32; o <<= 1) {
        int t = __shfl_up_sync(0xffffffffu, inc, o);
        if (lane >= o) inc += t;
    }
    if (lane == 31) wsum[w] = inc;
    __syncthreads();
    if (w == 0) {
        int s = wsum[lane];
        int si = s;
        #pragma unroll
        for (int o = 1; o < 32; o <<= 1) {
            int t = __shfl_up_sync(0xffffffffu, si, o);
            if (lane >= o) si += t;
        }
        wsum[lane] = si - s;
    }
    __syncthreads();
    int excl = wsum[w] + inc - v;
    if (i < NN) g_off[i] = excl;
    if (threadIdx.x == 1023) g_bsum[blockIdx.x] = excl + v;
}
__global__ void k_scan2() {
    __shared__ int sh[2];
    int t = threadIdx.x, lane = t & 31, w = t >> 5;
    int v = (t < NBLK) ? g_bsum[t] : 0;
    int inc = v;
    #pragma unroll
    for (int o = 1; o < 32; o <<= 1) {
        int x = __shfl_up_sync(0xffffffffu, inc, o);
        if (lane >= o) inc += x;
    }
    if (lane == 31) sh[w] = inc;
    __syncthreads();
    int add = (w == 1) ? sh[0] : 0;
    int excl = inc - v + add;
    if (t < NBLK) g_bsumx[t] = excl;
    if (t == NBLK - 1) g_off[NN] = excl + v;
}
__global__ void k_scan3() {
    int i = blockIdx.x * blockDim.x + threadIdx.x;
    if (i < NN) {
        int o = g_off[i] + g_bsumx[i >> 10];
        g_off[i] = o;
        g_cur[i] = o;
    }
}
__global__ void k_scatter(const int* __restrict__ src, const int* __restrict__ dst) {
    int e = blockIdx.x * blockDim.x + threadIdx.x;
    if (e >= EE) return;
    int p = atomicAdd(&g_cur[dst[e]], 1);
    g_esrc[p] = src[e];
}

// ---------------- weight transpose + bf16 split ----------------
template <int K>
__global__ void k_prep_w(const float* __restrict__ W,
                         __nv_bfloat16* __restrict__ oh, __nv_bfloat16* __restrict__ ol) {
    int i = blockIdx.x * blockDim.x + threadIdx.x;
    if (i >= HH * K) return;
    int n = i & (HH - 1), k = i >> 8;
    float v = W[k * HH + n];
    __nv_bfloat16 h, l;
    split_bf16(v, h, l);
    oh[n * K + k] = h;
    ol[n * K + k] = l;
}

// ---------------- BN0 fold ----------------
__global__ void k_colstats0(const float* __restrict__ A,
                            const float* __restrict__ fs, const float* __restrict__ fb) {
    int c = threadIdx.x;
    float scale = fs[c], bias = fb[c];
    float s = 0.0f, q = 0.0f;
    for (int r = blockIdx.x; r < NN; r += gridDim.x) {
        float v = A[(size_t)r * DIN + c] * scale + bias;
        s += v; q += v * v;
    }
    atomicAdd(&g_stats[c], s);
    atomicAdd(&g_stats[256 + c], q);
}
// fold s0/t0 (threads 0..127) then e[n] (all 256), one block
__global__ void k_folde(const float* __restrict__ fs, const float* __restrict__ fb,
                        const float* __restrict__ g,  const float* __restrict__ b,
                        const float* __restrict__ W1) {
    int t = threadIdx.x;
    if (t < DIN) {
        float mu  = g_stats[t] * (1.0f / NN);
        float var = g_stats[256 + t] * (1.0f / NN) - mu * mu;
        float a   = g[t] * rsqrtf(var + 1e-5f);
        g_s0[t] = fs[t] * a;
        g_t0[t] = (fb[t] - mu) * a + b[t];
    }
    __syncthreads();
    float e = 0.0f;
    #pragma unroll 8
    for (int k = 0; k < DIN; k++) e += g_t0[k] * W1[k * HH + t];
    g_e[t] = e;
}

// ---------------- GEMM1: single-chunk K=128, fp32 x with folded BN0 ----------------
__global__ __launch_bounds__(256)
void k_gemm1(const float* __restrict__ X,
             const __nv_bfloat16* __restrict__ Bh, const __nv_bfloat16* __restrict__ Bl,
             __half* __restrict__ C) {
    constexpr int LDS = 136;
    extern __shared__ __nv_bfloat16 sm[];
    const uint32_t A_HI = 0, A_LO = 128u * LDS * 2, B_HI = 2u * 128 * LDS * 2, B_LO = 3u * 128 * LDS * 2;
    char* smp = (char*)sm;

    const int tid = threadIdx.x, lane = tid & 31, wid = tid >> 5;
    const int wm = wid >> 1, wn = wid & 1;
    const int row0 = blockIdx.y * 128;
    const int n0   = blockIdx.x * 128;
    const uint32_t smb = smem_u32(sm);

    #pragma unroll
    for (int it = 0; it < 8; it++) {
        int idx = tid + it * 256;
        int r = idx >> 4, q = idx & 15;
        size_t go = (size_t)(n0 + r) * DIN + q * 8;
        uint32_t so = (uint32_t)(r * LDS + q * 8) * 2;
        cpa16(smb + B_HI + so, Bh + go, 16u);
        cpa16(smb + B_LO + so, Bl + go, 16u);
    }
    CP_COMMIT();

    #pragma unroll
    for (int it = 0; it < 16; it++) {
        int idx = tid + it * 256;
        int r = idx >> 5, q = idx & 31;
        int gr = row0 + r;
        float4 v = make_float4(0.f, 0.f, 0.f, 0.f);
        if (gr < NN) v = ((const float4*)X)[(size_t)gr * 32 + q];
        float4 s4 = ((const float4*)g_s0)[q];
        v.x *= s4.x; v.y *= s4.y; v.z *= s4.z; v.w *= s4.w;
        __nv_bfloat16 h[4], l[4];
        split_bf16(v.x, h[0], l[0]); split_bf16(v.y, h[1], l[1]);
        split_bf16(v.z, h[2], l[2]); split_bf16(v.w, h[3], l[3]);
        uint32_t off = (uint32_t)(r * LDS + q * 4) * 2;
        *(uint2*)(smp + A_HI + off) = *(uint2*)h;
        *(uint2*)(smp + A_LO + off) = *(uint2*)l;
    }
    asm volatile("cp.async.wait_group 0;" ::: "memory");
    __syncthreads();

    float c[2][8][4] = {};
    const int a_row = wm * 32 + (lane & 15);
    const int a_kof = (lane >> 4) * 8;
    const int b_row = wn * 64 + ((lane >> 4) << 3) + (lane & 7);
    const int b_kof = ((lane >> 3) & 1) * 8;

    #pragma unroll
    for (int k16 = 0; k16 < 8; k16++) {
        uint32_t ah[2][4], al[2][4];
        #pragma unroll
        for (int mt = 0; mt < 2; mt++) {
            uint32_t ro = ((a_row + mt * 16) * LDS + k16 * 16 + a_kof) * 2;
            ldm4(ah[mt], smb + A_HI + ro);
            ldm4(al[mt], smb + A_LO + ro);
        }
        uint32_t bh[8][2], bl[8][2];
        #pragma unroll
        for (int p = 0; p < 4; p++) {
            uint32_t ro = ((b_row + p * 16) * LDS + k16 * 16 + b_kof) * 2;
            uint32_t r4[4];
            ldm4(r4, smb + B_HI + ro);
            bh[2*p][0]=r4[0]; bh[2*p][1]=r4[1]; bh[2*p+1][0]=r4[2]; bh[2*p+1][1]=r4[3];
            ldm4(r4, smb + B_LO + ro);
            bl[2*p][0]=r4[0]; bl[2*p][1]=r4[1]; bl[2*p+1][0]=r4[2]; bl[2*p+1][1]=r4[3];
        }
        #pragma unroll
        for (int mt = 0; mt < 2; mt++)
            #pragma unroll
            for (int nt = 0; nt < 8; nt++) {
                mma16816(c[mt][nt], ah[mt], bh[nt]);
                mma16816(c[mt][nt], al[mt], bh[nt]);
                mma16816(c[mt][nt], ah[mt], bl[nt]);
            }
    }

    const int g = lane >> 2, t = lane & 3;
    #pragma unroll
    for (int mt = 0; mt < 2; mt++) {
        int rbase = row0 + wm * 32 + mt * 16;
        int r1w = rbase + g, r2w = rbase + g + 8;
        float s1 = (r1w < NN) ? g_dinv[r1w] : 0.0f;
        float s2 = (r2w < NN) ? g_dinv[r2w] : 0.0f;
        #pragma unroll
        for (int nt = 0; nt < 8; nt++) {
            int col = n0 + wn * 64 + nt * 8 + 2 * t;
            float2 ev = *(const float2*)(g_e + col);
            if (r1w < NN)
                *(__half2*)(C + (size_t)r1w * HH + col) =
                    __floats2half2_rn((c[mt][nt][0] + ev.x) * s1, (c[mt][nt][1] + ev.y) * s1);
            if (r2w < NN)
                *(__half2*)(C + (size_t)r2w * HH + col) =
                    __floats2half2_rn((c[mt][nt][2] + ev.x) * s2, (c[mt][nt][3] + ev.y) * s2);
        }
    }
}

// ---------------- GEMM2: K=256, bf16-split inputs, cp.async 2-stage ----------------
__global__ __launch_bounds__(256)
void k_gemm2(const __nv_bfloat16* __restrict__ Ah, const __nv_bfloat16* __restrict__ Al,
             const __nv_bfloat16* __restrict__ Bh, const __nv_bfloat16* __restrict__ Bl,
             __half* __restrict__ C) {
    constexpr int K = HH, BK = 64, NCH = K / BK;
    constexpr int LDS = 72;
    constexpr int STG = 4 * 128 * LDS;
    extern __shared__ __nv_bfloat16 sm[];

    const int tid = threadIdx.x, lane = tid & 31, wid = tid >> 5;
    const int wm = wid >> 1, wn = wid & 1;
    const int row0 = blockIdx.y * 128;
    const int n0   = blockIdx.x * 128;
    const uint32_t smb = smem_u32(sm);

    float c[2][8][4] = {};

    const int a_row = wm * 32 + (lane & 15);
    const int a_kof = (lane >> 4) * 8;
    const int b_row = wn * 64 + ((lane >> 4) << 3) + (lane & 7);
    const int b_kof = ((lane >> 3) & 1) * 8;

    auto load_stage = [&](int ch, int buf) {
        const uint32_t sb = smb + (uint32_t)buf * STG * 2;
        #pragma unroll
        for (int it = 0; it < 4; it++) {
            int idx = tid + it * 256;
            int r = idx >> 3, q = idx & 7;
            int gr = row0 + r;
            uint32_t vld = (gr < NN) ? 16u : 0u;
            int grc = gr < NN ? gr : NN - 1;
            size_t go = (size_t)grc * K + ch * BK + q * 8;
            uint32_t so = (uint32_t)(r * LDS + q * 8) * 2;
            cpa16(sb + so, Ah + go, vld);
            cpa16(sb + 128 * LDS * 2 + so, Al + go, vld);
        }
        #pragma unroll
        for (int it = 0; it < 4; it++) {
            int idx = tid + it * 256;
            int r = idx >> 3, q = idx & 7;
            size_t go = (size_t)(n0 + r) * K + ch * BK + q * 8;
            uint32_t so = (uint32_t)(r * LDS + q * 8) * 2;
            cpa16(sb + 2 * 128 * LDS * 2 + so, Bh + go, 16u);
            cpa16(sb + 3 * 128 * LDS * 2 + so, Bl + go, 16u);
        }
        CP_COMMIT();
    };

    load_stage(0, 0);

    #pragma unroll
    for (int ch = 0; ch < NCH; ch++) {
        if (ch + 1 < NCH) {
            load_stage(ch + 1, (ch + 1) & 1);
            asm volatile("cp.async.wait_group 1;" ::: "memory");
        } else {
            asm volatile("cp.async.wait_group 0;" ::: "memory");
        }
        __syncthreads();

        const uint32_t sbase = smb + (uint32_t)(ch & 1) * STG * 2;
        #pragma unroll
        for (int k16 = 0; k16 < BK / 16; k16++) {
            uint32_t ah[2][4], al[2][4];
            #pragma unroll
            for (int mt = 0; mt < 2; mt++) {
                uint32_t ro = ((a_row + mt * 16) * LDS + k16 * 16 + a_kof) * 2;
                ldm4(ah[mt], sbase + ro);
                ldm4(al[mt], sbase + 128 * LDS * 2 + ro);
            }
            uint32_t bh[8][2], bl[8][2];
            #pragma unroll
            for (int p = 0; p < 4; p++) {
                uint32_t ro = ((b_row + p * 16) * LDS + k16 * 16 + b_kof) * 2;
                uint32_t r4[4];
                ldm4(r4, sbase + 2 * 128 * LDS * 2 + ro);
                bh[2*p][0]=r4[0]; bh[2*p][1]=r4[1]; bh[2*p+1][0]=r4[2]; bh[2*p+1][1]=r4[3];
                ldm4(r4, sbase + 3 * 128 * LDS * 2 + ro);
                bl[2*p][0]=r4[0]; bl[2*p][1]=r4[1]; bl[2*p+1][0]=r4[2]; bl[2*p+1][1]=r4[3];
            }
            #pragma unroll
            for (int mt = 0; mt < 2; mt++)
                #pragma unroll
                for (int nt = 0; nt < 8; nt++) {
                    mma16816(c[mt][nt], ah[mt], bh[nt]);
                    mma16816(c[mt][nt], al[mt], bh[nt]);
                    mma16816(c[mt][nt], ah[mt], bl[nt]);
                }
        }
        __syncthreads();
    }

    const int g = lane >> 2, t = lane & 3;
    #pragma unroll
    for (int mt = 0; mt < 2; mt++) {
        int rbase = row0 + wm * 32 + mt * 16;
        int r1w = rbase + g, r2w = rbase + g + 8;
        float s1 = (r1w < NN) ? g_dinv[r1w] : 0.0f;
        float s2 = (r2w < NN) ? g_dinv[r2w] : 0.0f;
        #pragma unroll
        for (int nt = 0; nt < 8; nt++) {
            int col = n0 + wn * 64 + nt * 8 + 2 * t;
            if (r1w < NN)
                *(__half2*)(C + (size_t)r1w * HH + col) =
                    __floats2half2_rn(c[mt][nt][0] * s1, c[mt][nt][1] * s1);
            if (r2w < NN)
                *(__half2*)(C + (size_t)r2w * HH + col) =
                    __floats2half2_rn(c[mt][nt][2] * s2, c[mt][nt][3] * s2);
        }
    }
}

// ---------------- GCN aggregation (coalesced idx + shfl, 4x unrolled) ----------
__global__ __launch_bounds__(256)
void k_aggregate(const __half* __restrict__ hw, const float* __restrict__ bias,
                 float* __restrict__ out, float* __restrict__ stats) {
    __shared__ float red[8][256];
    int d    = (blockIdx.x * blockDim.x + threadIdx.x) >> 5;
    int lane = threadIdx.x & 31;
    int wid  = threadIdx.x >> 5;

    float acc[8] = {};
    const int beg = g_off[d], end = g_off[d + 1];

    int p0 = beg;
    while (p0 < end) {
        int cnt = end - p0;
        if (cnt > 32) cnt = 32;
        int idxv = (lane < cnt) ? g_esrc[p0 + lane] : 0;
        int j = 0;
        for (; j + 4 <= cnt; j += 4) {
            int s0 = __shfl_sync(0xffffffffu, idxv, j);
            int s1 = __shfl_sync(0xffffffffu, idxv, j + 1);
            int s2 = __shfl_sync(0xffffffffu, idxv, j + 2);
            int s3 = __shfl_sync(0xffffffffu, idxv, j + 3);
            acc_edge(acc, hw, s0, lane);
            acc_edge(acc, hw, s1, lane);
            acc_edge(acc, hw, s2, lane);
            acc_edge(acc, hw, s3, lane);
        }
        for (; j < cnt; j++) {
            int s0 = __shfl_sync(0xffffffffu, idxv, j);
            acc_edge(acc, hw, s0, lane);
        }
        p0 += cnt;
    }

    float di = g_dinv[d];
    float sv[8], bv[8], r[8];
    ldh8(sv, hw + (size_t)d * HH, lane);
    ld8(bv, bias, lane);
    #pragma unroll
    for (int i = 0; i < 8; i++)
        r[i] = fmaxf(di * (acc[i] + sv[i]) + bv[i], 0.0f);
    st8(out + (size_t)d * HH, lane, r);

    st8(&red[wid][0], lane, r);
    __syncthreads();
    int cidx = threadIdx.x;
    float s = 0.f, q = 0.f;
    #pragma unroll
    for (int w = 0; w < 8; w++) {
        float v = red[w][cidx];
        s += v; q += v * v;
    }
    atomicAdd(&stats[cidx], s);
    atomicAdd(&stats[256 + cidx], q);
}

// ---------------- BN -> LN -> bf16 split only (layer 1) ----------------
__global__ __launch_bounds__(256)
void k_bn_ln1(const float* __restrict__ t, const float* __restrict__ stats,
              const float* __restrict__ bng, const float* __restrict__ bnb,
              const float* __restrict__ lng, const float* __restrict__ lnb) {
    int row  = (blockIdx.x * blockDim.x + threadIdx.x) >> 5;
    int lane = threadIdx.x & 31;
    if (row >= NN) return;

    float v[8], s[8], q[8], g[8], b[8];
    ld8(v, t + (size_t)row * HH, lane);
    ld8(s, stats, lane);
    ld8(q, stats + 256, lane);
    ld8(g, bng, lane);
    ld8(b, bnb, lane);

    #pragma unroll
    for (int i = 0; i < 8; i++) {
        float mu  = s[i] * (1.0f / NN);
        float var = q[i] * (1.0f / NN) - mu * mu;
        v[i] = g[i] * (v[i] - mu) * rsqrtf(var + 1e-5f) + b[i];
    }

    float sum = 0.f;
    #pragma unroll
    for (int i = 0; i < 8; i++) sum += v[i];
    #pragma unroll
    for (int o = 16; o; o >>= 1) sum += __shfl_xor_sync(0xffffffffu, sum, o);
    float mu = sum * (1.0f / HH);

    float ss = 0.f;
    #pragma unroll
    for (int i = 0; i < 8; i++) { float dd = v[i] - mu; ss += dd * dd; }
    #pragma unroll
    for (int o = 16; o; o >>= 1) ss += __shfl_xor_sync(0xffffffffu, ss, o);
    float rs = rsqrtf(ss * (1.0f / HH) + 1e-5f);

    ld8(g, lng, lane);
    ld8(b, lnb, lane);
    #pragma unroll
    for (int i = 0; i < 8; i++) v[i] = g[i] * (v[i] - mu) * rs + b[i];

    // splits only — residual later reconstructed as h + l
    #pragma unroll
    for (int half = 0; half < 2; half++) {
        size_t o = (size_t)row * HH + half * 128 + lane * 4;
        __nv_bfloat16 h[4], l[4];
        #pragma unroll
        for (int i = 0; i < 4; i++) split_bf16(v[half * 4 + i], h[i], l[i]);
        *(uint2*)(g_a2h + o) = *(uint2*)h;
        *(uint2*)(g_a2l + o) = *(uint2*)l;
    }
}

// ---------------- final: BN -> LN -> +residual(split) -> out-proj ----------------
__global__ __launch_bounds__(256)
void k_bn_ln_out(const float* __restrict__ t, const float* __restrict__ stats,
                 const float* __restrict__ bng, const float* __restrict__ bnb,
                 const float* __restrict__ lng, const float* __restrict__ lnb,
                 const float* __restrict__ Wout, const float* __restrict__ bout,
                 float* __restrict__ out) {
    int row  = (blockIdx.x * blockDim.x + threadIdx.x) >> 5;
    int lane = threadIdx.x & 31;
    if (row >= NN) return;

    float v[8], s[8], q[8], g[8], b[8];
    ld8(v, t + (size_t)row * HH, lane);
    ld8(s, stats, lane);
    ld8(q, stats + 256, lane);
    ld8(g, bng, lane);
    ld8(b, bnb, lane);

    #pragma unroll
    for (int i = 0; i < 8; i++) {
        float mu  = s[i] * (1.0f / NN);
        float var = q[i] * (1.0f / NN) - mu * mu;
        v[i] = g[i] * (v[i] - mu) * rsqrtf(var + 1e-5f) + b[i];
    }

    float sum = 0.f;
    #pragma unroll
    for (int i = 0; i < 8; i++) sum += v[i];
    #pragma unroll
    for (int o = 16; o; o >>= 1) sum += __shfl_xor_sync(0xffffffffu, sum, o);
    float mu = sum * (1.0f / HH);

    float ss = 0.f;
    #pragma unroll
    for (int i = 0; i < 8; i++) { float dd = v[i] - mu; ss += dd * dd; }
    #pragma unroll
    for (int o = 16; o; o >>= 1) ss += __shfl_xor_sync(0xffffffffu, ss, o);
    float rs = rsqrtf(ss * (1.0f / HH) + 1e-5f);

    ld8(g, lng, lane);
    ld8(b, lnb, lane);
    float r[8];
    ldsplit8(r, g_a2h + (size_t)row * HH, g_a2l + (size_t)row * HH, lane);
    #pragma unroll
    for (int i = 0; i < 8; i++) v[i] = g[i] * (v[i] - mu) * rs + b[i] + r[i];

    const float4* W4 = (const float4*)Wout;
    float4 wA = W4[2 * lane],      wB = W4[2 * lane + 1];
    float4 wC = W4[64 + 2 * lane], wD = W4[65 + 2 * lane];
    float a0 = v[0]*wA.x + v[1]*wA.z + v[2]*wB.x + v[3]*wB.z
             + v[4]*wC.x + v[5]*wC.z + v[6]*wD.x + v[7]*wD.z;
    float a1 = v[0]*wA.y + v[1]*wA.w + v[2]*wB.y + v[3]*wB.w
             + v[4]*wC.y + v[5]*wC.w + v[6]*wD.y + v[7]*wD.w;
    #pragma unroll
    for (int o = 16; o; o >>= 1) {
        a0 += __shfl_xor_sync(0xffffffffu, a0, o);
        a1 += __shfl_xor_sync(0xffffffffu, a1, o);
    }
    if (lane == 0) {
        out[2 * row]     = a0 + bout[0];
        out[2 * row + 1] = a1 + bout[1];
    }
}

// ---------------- streams + events ----------------
static cudaStream_t g_s2, g_s3;
static cudaEvent_t  g_evF, g_evZ, g_evD, g_evJ, g_evW;
namespace {
struct _HxInit {
    _HxInit() {
        cudaStreamCreateWithFlags(&g_s2, cudaStreamNonBlocking);
        cudaStreamCreateWithFlags(&g_s3, cudaStreamNonBlocking);
        cudaEventCreateWithFlags(&g_evF, cudaEventDisableTiming);
        cudaEventCreateWithFlags(&g_evZ, cudaEventDisableTiming);
        cudaEventCreateWithFlags(&g_evD, cudaEventDisableTiming);
        cudaEventCreateWithFlags(&g_evJ, cudaEventDisableTiming);
        cudaEventCreateWithFlags(&g_evW, cudaEventDisableTiming);
    }
};
static _HxInit _hx_init;
}

// ---------------- launch ----------------
extern "C" void kernel_launch(void* const* d_in, const int* in_sizes, int n_in,
                              void* d_out, int out_size) {
    const float* x    = (const float*)d_in[0];
    const int*   ei   = (const int*)  d_in[1];
    const float* fs   = (const float*)d_in[2];
    const float* fb   = (const float*)d_in[3];
    const float* bn0g = (const float*)d_in[4];
    const float* bn0b = (const float*)d_in[5];
    const float* W1   = (const float*)d_in[6];
    const float* b1   = (const float*)d_in[7];
    const float* bn1g = (const float*)d_in[8];
    const float* bn1b = (const float*)d_in[9];
    const float* ln1g = (const float*)d_in[10];
    const float* ln1b = (const float*)d_in[11];
    const float* W2   = (const float*)d_in[12];
    const float* b2   = (const float*)d_in[13];
    const float* bn2g = (const float*)d_in[14];
    const float* bn2b = (const float*)d_in[15];
    const float* ln2g = (const float*)d_in[16];
    const float* ln2b = (const float*)d_in[17];
    const float* Wout = (const float*)d_in[18];
    const float* bout = (const float*)d_in[19];
    float* out = (float*)d_out;

    const int* srcp = ei;
    const int* dstp = ei + EE;

    __half* p_hw;
    float *p_h1, *p_h2, *p_stats;
    cudaGetSymbolAddress((void**)&p_hw, g_hw);
    cudaGetSymbolAddress((void**)&p_h1, g_h1);
    cudaGetSymbolAddress((void**)&p_h2, g_h2);
    cudaGetSymbolAddress((void**)&p_stats, g_stats);
    __nv_bfloat16 *p_a2h, *p_a2l, *p_w1h, *p_w1l, *p_w2h, *p_w2l;
    cudaGetSymbolAddress((void**)&p_a2h, g_a2h);
    cudaGetSymbolAddress((void**)&p_a2l, g_a2l);
    cudaGetSymbolAddress((void**)&p_w1h, g_w1h);
    cudaGetSymbolAddress((void**)&p_w1l, g_w1l);
    cudaGetSymbolAddress((void**)&p_w2h, g_w2h);
    cudaGetSymbolAddress((void**)&p_w2l, g_w2l);

    const int G1_SMEM = 4 * 128 * 136 * 2;        // 139264
    const int G2_SMEM = 2 * 4 * 128 * 72 * 2;     // 147456
    cudaFuncSetAttribute(k_gemm1, cudaFuncAttributeMaxDynamicSharedMemorySize, G1_SMEM);
    cudaFuncSetAttribute(k_gemm2, cudaFuncAttributeMaxDynamicSharedMemorySize, G2_SMEM);

    const int WARP_GRID = (NN * 32 + 255) / 256;  // 6250
    const dim3 MGRID(2, (NN + 127) / 128);

    // ---- fork ----
    cudaEventRecord(g_evF, 0);
    cudaStreamWaitEvent(g_s2, g_evF, 0);
    cudaStreamWaitEvent(g_s3, g_evF, 0);

    // side stream 2: stats zero + graph preprocessing
    k_zero_all<<<6, 256, 0, g_s2>>>();
    cudaEventRecord(g_evZ, g_s2);
    k_zero_deg<<<(NN + 255) / 256, 256, 0, g_s2>>>();
    k_count<<<(EE + 255) / 256, 256, 0, g_s2>>>(dstp);
    k_dinv<<<(NN + 255) / 256, 256, 0, g_s2>>>();
    cudaEventRecord(g_evD, g_s2);
    k_scan1<<<NBLK, 1024, 0, g_s2>>>();
    k_scan2<<<1, 64, 0, g_s2>>>();
    k_scan3<<<(NN + 1023) / 1024, 1024, 0, g_s2>>>();
    k_scatter<<<(EE + 255) / 256, 256, 0, g_s2>>>(srcp, dstp);
    cudaEventRecord(g_evJ, g_s2);

    // side stream 3: weight prep
    k_prep_w<DIN><<<(HH * DIN + 255) / 256, 256, 0, g_s3>>>(W1, p_w1h, p_w1l);
    k_prep_w<HH><<<(HH * HH + 255) / 256, 256, 0, g_s3>>>(W2, p_w2h, p_w2l);
    cudaEventRecord(g_evW, g_s3);

    // ---- main stream ----
    cudaStreamWaitEvent(0, g_evZ, 0);
    k_colstats0<<<1024, DIN>>>(x, fs, fb);
    k_folde<<<1, HH>>>(fs, fb, bn0g, bn0b, W1);

    // layer 1 (BN0 folded into GEMM1)
    cudaStreamWaitEvent(0, g_evD, 0);
    cudaStreamWaitEvent(0, g_evW, 0);
    k_gemm1<<<MGRID, 256, G1_SMEM>>>(x, p_w1h, p_w1l, p_hw);
    cudaStreamWaitEvent(0, g_evJ, 0);
    k_aggregate<<<WARP_GRID, 256>>>(p_hw, b1, p_h1, p_stats + 512);
    k_bn_ln1<<<WARP_GRID, 256>>>(p_h1, p_stats + 512, bn1g, bn1b, ln1g, ln1b);

    // layer 2 (+ residual from splits, + fused output projection)
    k_gemm2<<<MGRID, 256, G2_SMEM>>>(p_a2h, p_a2l, p_w2h, p_w2l, p_hw);
    k_aggregate<<<WARP_GRID, 256>>>(p_hw, b2, p_h2, p_stats + 1024);
    k_bn_ln_out<<<WARP_GRID, 256>>>(p_h2, p_stats + 1024,
                                    bn2g, bn2b, ln2g, ln2b,
                                    Wout, bout, out);
}

// round 11
// speedup vs baseline: 1.1699x; 1.0238x over previous
#include <cuda_runtime.h>
#include <cuda_bf16.h>
#include <cuda_fp16.h>
#include <cstdint>
#include <cstddef>

#define NN  50000
#define EE  800000
#define DIN 128
#define HH  256
#define NBLK 49   // ceil(NN/1024)

// ---------------- static device scratch ----------------
__device__ __align__(16) __half g_hw[(size_t)NN * HH];     // GEMM output, dinv-scaled, fp16
__device__ __align__(16) __half g_h1[(size_t)NN * HH];     // agg1 output (fp16)
__device__ __align__(16) __half g_h2[(size_t)NN * HH];     // agg2 output (fp16)
__device__ __align__(16) float g_stats[1536];
__device__ __align__(16) float g_s0[DIN];
__device__ __align__(16) float g_t0[DIN];
__device__ __align__(16) float g_e[HH];
__device__ float g_dinv[NN];
__device__ int   g_deg[NN];
__device__ int   g_off[NN + 1];
__device__ int   g_cur[NN];
__device__ int   g_esrc[EE];
__device__ int   g_bsum[NBLK];
__device__ int   g_bsumx[NBLK];
// bf16 split of post-LN h1 — GEMM2 A operand AND residual source
__device__ __align__(16) __nv_bfloat16 g_a2h[(size_t)NN * HH];
__device__ __align__(16) __nv_bfloat16 g_a2l[(size_t)NN * HH];
__device__ __align__(16) __nv_bfloat16 g_w1h[HH * DIN];
__device__ __align__(16) __nv_bfloat16 g_w1l[HH * DIN];
__device__ __align__(16) __nv_bfloat16 g_w2h[HH * HH];
__device__ __align__(16) __nv_bfloat16 g_w2l[HH * HH];

// ---------------- helpers ----------------
__device__ __forceinline__ uint32_t smem_u32(const void* p) {
    uint32_t a;
    asm("{ .reg .u64 t; cvta.to.shared.u64 t, %1; cvt.u32.u64 %0, t; }" : "=r"(a) : "l"(p));
    return a;
}
__device__ __forceinline__ void ldm4(uint32_t* r, uint32_t addr) {
    asm volatile("ldmatrix.sync.aligned.m8n8.x4.shared.b16 {%0,%1,%2,%3}, [%4];"
                 : "=r"(r[0]), "=r"(r[1]), "=r"(r[2]), "=r"(r[3]) : "r"(addr));
}
__device__ __forceinline__ void mma16816(float* c, const uint32_t* a, const uint32_t* b) {
    asm volatile("mma.sync.aligned.m16n8k16.row.col.f32.bf16.bf16.f32 "
                 "{%0,%1,%2,%3}, {%4,%5,%6,%7}, {%8,%9}, {%0,%1,%2,%3};"
                 : "+f"(c[0]), "+f"(c[1]), "+f"(c[2]), "+f"(c[3])
                 : "r"(a[0]), "r"(a[1]), "r"(a[2]), "r"(a[3]), "r"(b[0]), "r"(b[1]));
}
__device__ __forceinline__ void cpa16(uint32_t dst, const void* src, uint32_t vld) {
    asm volatile("cp.async.cg.shared.global [%0], [%1], 16, %2;"
                 :: "r"(dst), "l"(src), "r"(vld) : "memory");
}
#define CP_COMMIT() asm volatile("cp.async.commit_group;" ::: "memory")

__device__ __forceinline__ void ld8(float* o, const float* p, int lane) {
    float4 a = ((const float4*)p)[lane];
    float4 b = ((const float4*)p)[32 + lane];
    o[0]=a.x; o[1]=a.y; o[2]=a.z; o[3]=a.w;
    o[4]=b.x; o[5]=b.y; o[6]=b.z; o[7]=b.w;
}
__device__ __forceinline__ void st8(float* p, int lane, const float* v) {
    ((float4*)p)[lane]      = make_float4(v[0], v[1], v[2], v[3]);
    ((float4*)p)[32 + lane] = make_float4(v[4], v[5], v[6], v[7]);
}
__device__ __forceinline__ void ldh8(float* o, const __half* p, int lane) {
    uint2 a = __ldg((const uint2*)p + lane);
    uint2 b = __ldg((const uint2*)p + 32 + lane);
    float2 f;
    f = __half22float2(*(__half2*)&a.x); o[0]=f.x; o[1]=f.y;
    f = __half22float2(*(__half2*)&a.y); o[2]=f.x; o[3]=f.y;
    f = __half22float2(*(__half2*)&b.x); o[4]=f.x; o[5]=f.y;
    f = __half22float2(*(__half2*)&b.y); o[6]=f.x; o[7]=f.y;
}
// store 8 floats as fp16 into a 256-col row
__device__ __forceinline__ void sth8(__half* p, int lane, const float* v) {
    uint2 a, b;
    *(__half2*)&a.x = __floats2half2_rn(v[0], v[1]);
    *(__half2*)&a.y = __floats2half2_rn(v[2], v[3]);
    *(__half2*)&b.x = __floats2half2_rn(v[4], v[5]);
    *(__half2*)&b.y = __floats2half2_rn(v[6], v[7]);
    ((uint2*)p)[lane]      = a;
    ((uint2*)p)[32 + lane] = b;
}
// load 8 floats reconstructed from a bf16 hi/lo split pair
__device__ __forceinline__ void ldsplit8(float* o, const __nv_bfloat16* ph,
                                         const __nv_bfloat16* pl, int lane) {
    uint2 hA = __ldg((const uint2*)ph + lane);
    uint2 hB = __ldg((const uint2*)ph + 32 + lane);
    uint2 lA = __ldg((const uint2*)pl + lane);
    uint2 lB = __ldg((const uint2*)pl + 32 + lane);
    const __nv_bfloat16* h = (const __nv_bfloat16*)&hA;
    const __nv_bfloat16* l = (const __nv_bfloat16*)&lA;
    #pragma unroll
    for (int i = 0; i < 4; i++) o[i] = __bfloat162float(h[i]) + __bfloat162float(l[i]);
    h = (const __nv_bfloat16*)&hB;
    l = (const __nv_bfloat16*)&lB;
    #pragma unroll
    for (int i = 0; i < 4; i++) o[4 + i] = __bfloat162float(h[i]) + __bfloat162float(l[i]);
}
__device__ __forceinline__ void split_bf16(float v, __nv_bfloat16& h, __nv_bfloat16& l) {
    h = __float2bfloat16_rn(v);
    l = __float2bfloat16_rn(v - __bfloat162float(h));
}
__device__ __forceinline__ void acc_edge(float* acc, const __half* hw, int s, int lane) {
    const uint2* rp = (const uint2*)(hw + (size_t)s * HH);
    uint2 a = __ldg(rp + lane);
    uint2 b = __ldg(rp + 32 + lane);
    float2 f;
    f = __half22float2(*(__half2*)&a.x); acc[0] += f.x; acc[1] += f.y;
    f = __half22float2(*(__half2*)&a.y); acc[2] += f.x; acc[3] += f.y;
    f = __half22float2(*(__half2*)&b.x); acc[4] += f.x; acc[5] += f.y;
    f = __half22float2(*(__half2*)&b.y); acc[6] += f.x; acc[7] += f.y;
}

// ---------------- graph preprocessing ----------------
__global__ void k_zero_all() {
    int i = blockIdx.x * blockDim.x + threadIdx.x;
    if (i < 1536) g_stats[i] = 0.0f;
}
__global__ void k_zero_deg() {
    int i = blockIdx.x * blockDim.x + threadIdx.x;
    if (i < NN) g_deg[i] = 0;
}
__global__ void k_count(const int* __restrict__ dst) {
    int e = blockIdx.x * blockDim.x + threadIdx.x;
    if (e < EE) atomicAdd(&g_deg[dst[e]], 1);
}
__global__ void k_dinv() {
    int i = blockIdx.x * blockDim.x + threadIdx.x;
    if (i < NN) g_dinv[i] = rsqrtf((float)g_deg[i] + 1.0f);
}
__global__ void k_scan1() {
    __shared__ int wsum[32];
    int i = blockIdx.x * 1024 + threadIdx.x;
    int lane = threadIdx.x & 31, w = threadIdx.x >> 5;
    int v = (i < NN) ? g_deg[i] : 0;
    int inc = v;
    #pragma unroll
    for (int o = 1; o < 32; o <<= 1) {
        int t = __shfl_up_sync(0xffffffffu, inc, o);
        if (lane >= o) inc += t;
    }
    if (lane == 31) wsum[w] = inc;
    __syncthreads();
    if (w == 0) {
        int s = wsum[lane];
        int si = s;
        #pragma unroll
        for (int o = 1; o < 32; o <<= 1) {
            int t = __shfl_up_sync(0xffffffffu, si, o);
            if (lane >= o) si += t;
        }
        wsum[lane] = si - s;
    }
    __syncthreads();
    int excl = wsum[w] + inc - v;
    if (i < NN) g_off[i] = excl;
    if (threadIdx.x == 1023) g_bsum[blockIdx.x] = excl + v;
}
__global__ void k_scan2() {
    __shared__ int sh[2];
    int t = threadIdx.x, lane = t & 31, w = t >> 5;
    int v = (t < NBLK) ? g_bsum[t] : 0;
    int inc = v;
    #pragma unroll
    for (int o = 1; o < 32; o <<= 1) {
        int x = __shfl_up_sync(0xffffffffu, inc, o);
        if (lane >= o) inc += x;
    }
    if (lane == 31) sh[w] = inc;
    __syncthreads();
    int add = (w == 1) ? sh[0] : 0;
    int excl = inc - v + add;
    if (t < NBLK) g_bsumx[t] = excl;
    if (t == NBLK - 1) g_off[NN] = excl + v;
}
__global__ void k_scan3() {
    int i = blockIdx.x * blockDim.x + threadIdx.x;
    if (i < NN) {
        int o = g_off[i] + g_bsumx[i >> 10];
        g_off[i] = o;
        g_cur[i] = o;
    }
}
__global__ void k_scatter(const int* __restrict__ src, const int* __restrict__ dst) {
    int e = blockIdx.x * blockDim.x + threadIdx.x;
    if (e >= EE) return;
    int p = atomicAdd(&g_cur[dst[e]], 1);
    g_esrc[p] = src[e];
}

// ---------------- weight transpose + bf16 split ----------------
template <int K>
__global__ void k_prep_w(const float* __restrict__ W,
                         __nv_bfloat16* __restrict__ oh, __nv_bfloat16* __restrict__ ol) {
    int i = blockIdx.x * blockDim.x + threadIdx.x;
    if (i >= HH * K) return;
    int n = i & (HH - 1), k = i >> 8;
    float v = W[k * HH + n];
    __nv_bfloat16 h, l;
    split_bf16(v, h, l);
    oh[n * K + k] = h;
    ol[n * K + k] = l;
}

// ---------------- BN0 fold ----------------
__global__ void k_colstats0(const float* __restrict__ A,
                            const float* __restrict__ fs, const float* __restrict__ fb) {
    int c = threadIdx.x;
    float scale = fs[c], bias = fb[c];
    float s = 0.0f, q = 0.0f;
    for (int r = blockIdx.x; r < NN; r += gridDim.x) {
        float v = A[(size_t)r * DIN + c] * scale + bias;
        s += v; q += v * v;
    }
    atomicAdd(&g_stats[c], s);
    atomicAdd(&g_stats[256 + c], q);
}
__global__ void k_folde(const float* __restrict__ fs, const float* __restrict__ fb,
                        const float* __restrict__ g,  const float* __restrict__ b,
                        const float* __restrict__ W1) {
    int t = threadIdx.x;
    if (t < DIN) {
        float mu  = g_stats[t] * (1.0f / NN);
        float var = g_stats[256 + t] * (1.0f / NN) - mu * mu;
        float a   = g[t] * rsqrtf(var + 1e-5f);
        g_s0[t] = fs[t] * a;
        g_t0[t] = (fb[t] - mu) * a + b[t];
    }
    __syncthreads();
    float e = 0.0f;
    #pragma unroll 8
    for (int k = 0; k < DIN; k++) e += g_t0[k] * W1[k * HH + t];
    g_e[t] = e;
}

// ---------------- GEMM1: single-chunk K=128, fp32 x with folded BN0 ----------------
__global__ __launch_bounds__(256)
void k_gemm1(const float* __restrict__ X,
             const __nv_bfloat16* __restrict__ Bh, const __nv_bfloat16* __restrict__ Bl,
             __half* __restrict__ C) {
    constexpr int LDS = 136;
    extern __shared__ __nv_bfloat16 sm[];
    const uint32_t A_HI = 0, A_LO = 128u * LDS * 2, B_HI = 2u * 128 * LDS * 2, B_LO = 3u * 128 * LDS * 2;
    char* smp = (char*)sm;

    const int tid = threadIdx.x, lane = tid & 31, wid = tid >> 5;
    const int wm = wid >> 1, wn = wid & 1;
    const int row0 = blockIdx.y * 128;
    const int n0   = blockIdx.x * 128;
    const uint32_t smb = smem_u32(sm);

    #pragma unroll
    for (int it = 0; it < 8; it++) {
        int idx = tid + it * 256;
        int r = idx >> 4, q = idx & 15;
        size_t go = (size_t)(n0 + r) * DIN + q * 8;
        uint32_t so = (uint32_t)(r * LDS + q * 8) * 2;
        cpa16(smb + B_HI + so, Bh + go, 16u);
        cpa16(smb + B_LO + so, Bl + go, 16u);
    }
    CP_COMMIT();

    #pragma unroll
    for (int it = 0; it < 16; it++) {
        int idx = tid + it * 256;
        int r = idx >> 5, q = idx & 31;
        int gr = row0 + r;
        float4 v = make_float4(0.f, 0.f, 0.f, 0.f);
        if (gr < NN) v = ((const float4*)X)[(size_t)gr * 32 + q];
        float4 s4 = ((const float4*)g_s0)[q];
        v.x *= s4.x; v.y *= s4.y; v.z *= s4.z; v.w *= s4.w;
        __nv_bfloat16 h[4], l[4];
        split_bf16(v.x, h[0], l[0]); split_bf16(v.y, h[1], l[1]);
        split_bf16(v.z, h[2], l[2]); split_bf16(v.w, h[3], l[3]);
        uint32_t off = (uint32_t)(r * LDS + q * 4) * 2;
        *(uint2*)(smp + A_HI + off) = *(uint2*)h;
        *(uint2*)(smp + A_LO + off) = *(uint2*)l;
    }
    asm volatile("cp.async.wait_group 0;" ::: "memory");
    __syncthreads();

    float c[2][8][4] = {};
    const int a_row = wm * 32 + (lane & 15);
    const int a_kof = (lane >> 4) * 8;
    const int b_row = wn * 64 + ((lane >> 4) << 3) + (lane & 7);
    const int b_kof = ((lane >> 3) & 1) * 8;

    #pragma unroll
    for (int k16 = 0; k16 < 8; k16++) {
        uint32_t ah[2][4], al[2][4];
        #pragma unroll
        for (int mt = 0; mt < 2; mt++) {
            uint32_t ro = ((a_row + mt * 16) * LDS + k16 * 16 + a_kof) * 2;
            ldm4(ah[mt], smb + A_HI + ro);
            ldm4(al[mt], smb + A_LO + ro);
        }
        uint32_t bh[8][2], bl[8][2];
        #pragma unroll
        for (int p = 0; p < 4; p++) {
            uint32_t ro = ((b_row + p * 16) * LDS + k16 * 16 + b_kof) * 2;
            uint32_t r4[4];
            ldm4(r4, smb + B_HI + ro);
            bh[2*p][0]=r4[0]; bh[2*p][1]=r4[1]; bh[2*p+1][0]=r4[2]; bh[2*p+1][1]=r4[3];
            ldm4(r4, smb + B_LO + ro);
            bl[2*p][0]=r4[0]; bl[2*p][1]=r4[1]; bl[2*p+1][0]=r4[2]; bl[2*p+1][1]=r4[3];
        }
        #pragma unroll
        for (int mt = 0; mt < 2; mt++)
            #pragma unroll
            for (int nt = 0; nt < 8; nt++) {
                mma16816(c[mt][nt], ah[mt], bh[nt]);
                mma16816(c[mt][nt], al[mt], bh[nt]);
                mma16816(c[mt][nt], ah[mt], bl[nt]);
            }
    }

    const int g = lane >> 2, t = lane & 3;
    #pragma unroll
    for (int mt = 0; mt < 2; mt++) {
        int rbase = row0 + wm * 32 + mt * 16;
        int r1w = rbase + g, r2w = rbase + g + 8;
        float s1 = (r1w < NN) ? g_dinv[r1w] : 0.0f;
        float s2 = (r2w < NN) ? g_dinv[r2w] : 0.0f;
        #pragma unroll
        for (int nt = 0; nt < 8; nt++) {
            int col = n0 + wn * 64 + nt * 8 + 2 * t;
            float2 ev = *(const float2*)(g_e + col);
            if (r1w < NN)
                *(__half2*)(C + (size_t)r1w * HH + col) =
                    __floats2half2_rn((c[mt][nt][0] + ev.x) * s1, (c[mt][nt][1] + ev.y) * s1);
            if (r2w < NN)
                *(__half2*)(C + (size_t)r2w * HH + col) =
                    __floats2half2_rn((c[mt][nt][2] + ev.x) * s2, (c[mt][nt][3] + ev.y) * s2);
        }
    }
}

// ---------------- GEMM2: K=256, bf16-split inputs, cp.async 2-stage ----------------
__global__ __launch_bounds__(256)
void k_gemm2(const __nv_bfloat16* __restrict__ Ah, const __nv_bfloat16* __restrict__ Al,
             const __nv_bfloat16* __restrict__ Bh, const __nv_bfloat16* __restrict__ Bl,
             __half* __restrict__ C) {
    constexpr int K = HH, BK = 64, NCH = K / BK;
    constexpr int LDS = 72;
    constexpr int STG = 4 * 128 * LDS;
    extern __shared__ __nv_bfloat16 sm[];

    const int tid = threadIdx.x, lane = tid & 31, wid = tid >> 5;
    const int wm = wid >> 1, wn = wid & 1;
    const int row0 = blockIdx.y * 128;
    const int n0   = blockIdx.x * 128;
    const uint32_t smb = smem_u32(sm);

    float c[2][8][4] = {};

    const int a_row = wm * 32 + (lane & 15);
    const int a_kof = (lane >> 4) * 8;
    const int b_row = wn * 64 + ((lane >> 4) << 3) + (lane & 7);
    const int b_kof = ((lane >> 3) & 1) * 8;

    auto load_stage = [&](int ch, int buf) {
        const uint32_t sb = smb + (uint32_t)buf * STG * 2;
        #pragma unroll
        for (int it = 0; it < 4; it++) {
            int idx = tid + it * 256;
            int r = idx >> 3, q = idx & 7;
            int gr = row0 + r;
            uint32_t vld = (gr < NN) ? 16u : 0u;
            int grc = gr < NN ? gr : NN - 1;
            size_t go = (size_t)grc * K + ch * BK + q * 8;
            uint32_t so = (uint32_t)(r * LDS + q * 8) * 2;
            cpa16(sb + so, Ah + go, vld);
            cpa16(sb + 128 * LDS * 2 + so, Al + go, vld);
        }
        #pragma unroll
        for (int it = 0; it < 4; it++) {
            int idx = tid + it * 256;
            int r = idx >> 3, q = idx & 7;
            size_t go = (size_t)(n0 + r) * K + ch * BK + q * 8;
            uint32_t so = (uint32_t)(r * LDS + q * 8) * 2;
            cpa16(sb + 2 * 128 * LDS * 2 + so, Bh + go, 16u);
            cpa16(sb + 3 * 128 * LDS * 2 + so, Bl + go, 16u);
        }
        CP_COMMIT();
    };

    load_stage(0, 0);

    #pragma unroll
    for (int ch = 0; ch < NCH; ch++) {
        if (ch + 1 < NCH) {
            load_stage(ch + 1, (ch + 1) & 1);
            asm volatile("cp.async.wait_group 1;" ::: "memory");
        } else {
            asm volatile("cp.async.wait_group 0;" ::: "memory");
        }
        __syncthreads();

        const uint32_t sbase = smb + (uint32_t)(ch & 1) * STG * 2;
        #pragma unroll
        for (int k16 = 0; k16 < BK / 16; k16++) {
            uint32_t ah[2][4], al[2][4];
            #pragma unroll
            for (int mt = 0; mt < 2; mt++) {
                uint32_t ro = ((a_row + mt * 16) * LDS + k16 * 16 + a_kof) * 2;
                ldm4(ah[mt], sbase + ro);
                ldm4(al[mt], sbase + 128 * LDS * 2 + ro);
            }
            uint32_t bh[8][2], bl[8][2];
            #pragma unroll
            for (int p = 0; p < 4; p++) {
                uint32_t ro = ((b_row + p * 16) * LDS + k16 * 16 + b_kof) * 2;
                uint32_t r4[4];
                ldm4(r4, sbase + 2 * 128 * LDS * 2 + ro);
                bh[2*p][0]=r4[0]; bh[2*p][1]=r4[1]; bh[2*p+1][0]=r4[2]; bh[2*p+1][1]=r4[3];
                ldm4(r4, sbase + 3 * 128 * LDS * 2 + ro);
                bl[2*p][0]=r4[0]; bl[2*p][1]=r4[1]; bl[2*p+1][0]=r4[2]; bl[2*p+1][1]=r4[3];
            }
            #pragma unroll
            for (int mt = 0; mt < 2; mt++)
                #pragma unroll
                for (int nt = 0; nt < 8; nt++) {
                    mma16816(c[mt][nt], ah[mt], bh[nt]);
                    mma16816(c[mt][nt], al[mt], bh[nt]);
                    mma16816(c[mt][nt], ah[mt], bl[nt]);
                }
        }
        __syncthreads();
    }

    const int g = lane >> 2, t = lane & 3;
    #pragma unroll
    for (int mt = 0; mt < 2; mt++) {
        int rbase = row0 + wm * 32 + mt * 16;
        int r1w = rbase + g, r2w = rbase + g + 8;
        float s1 = (r1w < NN) ? g_dinv[r1w] : 0.0f;
        float s2 = (r2w < NN) ? g_dinv[r2w] : 0.0f;
        #pragma unroll
        for (int nt = 0; nt < 8; nt++) {
            int col = n0 + wn * 64 + nt * 8 + 2 * t;
            if (r1w < NN)
                *(__half2*)(C + (size_t)r1w * HH + col) =
                    __floats2half2_rn(c[mt][nt][0] * s1, c[mt][nt][1] * s1);
            if (r2w < NN)
                *(__half2*)(C + (size_t)r2w * HH + col) =
                    __floats2half2_rn(c[mt][nt][2] * s2, c[mt][nt][3] * s2);
        }
    }
}

// ---------------- GCN aggregation (fp16 out) + fused BN column stats ----------
__global__ __launch_bounds__(256)
void k_aggregate(const __half* __restrict__ hw, const float* __restrict__ bias,
                 __half* __restrict__ out, float* __restrict__ stats) {
    __shared__ float red[8][256];
    int d    = (blockIdx.x * blockDim.x + threadIdx.x) >> 5;
    int lane = threadIdx.x & 31;
    int wid  = threadIdx.x >> 5;

    float acc[8] = {};
    const int beg = g_off[d], end = g_off[d + 1];

    int p0 = beg;
    while (p0 < end) {
        int cnt = end - p0;
        if (cnt > 32) cnt = 32;
        int idxv = (lane < cnt) ? g_esrc[p0 + lane] : 0;
        int j = 0;
        for (; j + 4 <= cnt; j += 4) {
            int s0 = __shfl_sync(0xffffffffu, idxv, j);
            int s1 = __shfl_sync(0xffffffffu, idxv, j + 1);
            int s2 = __shfl_sync(0xffffffffu, idxv, j + 2);
            int s3 = __shfl_sync(0xffffffffu, idxv, j + 3);
            acc_edge(acc, hw, s0, lane);
            acc_edge(acc, hw, s1, lane);
            acc_edge(acc, hw, s2, lane);
            acc_edge(acc, hw, s3, lane);
        }
        for (; j < cnt; j++) {
            int s0 = __shfl_sync(0xffffffffu, idxv, j);
            acc_edge(acc, hw, s0, lane);
        }
        p0 += cnt;
    }

    float di = g_dinv[d];
    float sv[8], bv[8], r[8];
    ldh8(sv, hw + (size_t)d * HH, lane);
    ld8(bv, bias, lane);
    #pragma unroll
    for (int i = 0; i < 8; i++)
        r[i] = fmaxf(di * (acc[i] + sv[i]) + bv[i], 0.0f);
    sth8(out + (size_t)d * HH, lane, r);

    st8(&red[wid][0], lane, r);
    __syncthreads();
    int cidx = threadIdx.x;
    float s = 0.f, q = 0.f;
    #pragma unroll
    for (int w = 0; w < 8; w++) {
        float v = red[w][cidx];
        s += v; q += v * v;
    }
    atomicAdd(&stats[cidx], s);
    atomicAdd(&stats[256 + cidx], q);
}

// ---------------- BN -> LN -> bf16 split only (layer 1) ----------------
__global__ __launch_bounds__(256)
void k_bn_ln1(const __half* __restrict__ t, const float* __restrict__ stats,
              const float* __restrict__ bng, const float* __restrict__ bnb,
              const float* __restrict__ lng, const float* __restrict__ lnb) {
    int row  = (blockIdx.x * blockDim.x + threadIdx.x) >> 5;
    int lane = threadIdx.x & 31;
    if (row >= NN) return;

    float v[8], s[8], q[8], g[8], b[8];
    ldh8(v, t + (size_t)row * HH, lane);
    ld8(s, stats, lane);
    ld8(q, stats + 256, lane);
    ld8(g, bng, lane);
    ld8(b, bnb, lane);

    #pragma unroll
    for (int i = 0; i < 8; i++) {
        float mu  = s[i] * (1.0f / NN);
        float var = q[i] * (1.0f / NN) - mu * mu;
        v[i] = g[i] * (v[i] - mu) * rsqrtf(var + 1e-5f) + b[i];
    }

    float sum = 0.f;
    #pragma unroll
    for (int i = 0; i < 8; i++) sum += v[i];
    #pragma unroll
    for (int o = 16; o; o >>= 1) sum += __shfl_xor_sync(0xffffffffu, sum, o);
    float mu = sum * (1.0f / HH);

    float ss = 0.f;
    #pragma unroll
    for (int i = 0; i < 8; i++) { float dd = v[i] - mu; ss += dd * dd; }
    #pragma unroll
    for (int o = 16; o; o >>= 1) ss += __shfl_xor_sync(0xffffffffu, ss, o);
    float rs = rsqrtf(ss * (1.0f / HH) + 1e-5f);

    ld8(g, lng, lane);
    ld8(b, lnb, lane);
    #pragma unroll
    for (int i = 0; i < 8; i++) v[i] = g[i] * (v[i] - mu) * rs + b[i];

    #pragma unroll
    for (int half = 0; half < 2; half++) {
        size_t o = (size_t)row * HH + half * 128 + lane * 4;
        __nv_bfloat16 h[4], l[4];
        #pragma unroll
        for (int i = 0; i < 4; i++) split_bf16(v[half * 4 + i], h[i], l[i]);
        *(uint2*)(g_a2h + o) = *(uint2*)h;
        *(uint2*)(g_a2l + o) = *(uint2*)l;
    }
}

// ---------------- final: BN -> LN -> +residual(split) -> out-proj ----------------
__global__ __launch_bounds__(256)
void k_bn_ln_out(const __half* __restrict__ t, const float* __restrict__ stats,
                 const float* __restrict__ bng, const float* __restrict__ bnb,
                 const float* __restrict__ lng, const float* __restrict__ lnb,
                 const float* __restrict__ Wout, const float* __restrict__ bout,
                 float* __restrict__ out) {
    int row  = (blockIdx.x * blockDim.x + threadIdx.x) >> 5;
    int lane = threadIdx.x & 31;
    if (row >= NN) return;

    float v[8], s[8], q[8], g[8], b[8];
    ldh8(v, t + (size_t)row * HH, lane);
    ld8(s, stats, lane);
    ld8(q, stats + 256, lane);
    ld8(g, bng, lane);
    ld8(b, bnb, lane);

    #pragma unroll
    for (int i = 0; i < 8; i++) {
        float mu  = s[i] * (1.0f / NN);
        float var = q[i] * (1.0f / NN) - mu * mu;
        v[i] = g[i] * (v[i] - mu) * rsqrtf(var + 1e-5f) + b[i];
    }

    float sum = 0.f;
    #pragma unroll
    for (int i = 0; i < 8; i++) sum += v[i];
    #pragma unroll
    for (int o = 16; o; o >>= 1) sum += __shfl_xor_sync(0xffffffffu, sum, o);
    float mu = sum * (1.0f / HH);

    float ss = 0.f;
    #pragma unroll
    for (int i = 0; i < 8; i++) { float dd = v[i] - mu; ss += dd * dd; }
    #pragma unroll
    for (int o = 16; o; o >>= 1) ss += __shfl_xor_sync(0xffffffffu, ss, o);
    float rs = rsqrtf(ss * (1.0f / HH) + 1e-5f);

    ld8(g, lng, lane);
    ld8(b, lnb, lane);
    float r[8];
    ldsplit8(r, g_a2h + (size_t)row * HH, g_a2l + (size_t)row * HH, lane);
    #pragma unroll
    for (int i = 0; i < 8; i++) v[i] = g[i] * (v[i] - mu) * rs + b[i] + r[i];

    const float4* W4 = (const float4*)Wout;
    float4 wA = W4[2 * lane],      wB = W4[2 * lane + 1];
    float4 wC = W4[64 + 2 * lane], wD = W4[65 + 2 * lane];
    float a0 = v[0]*wA.x + v[1]*wA.z + v[2]*wB.x + v[3]*wB.z
             + v[4]*wC.x + v[5]*wC.z + v[6]*wD.x + v[7]*wD.z;
    float a1 = v[0]*wA.y + v[1]*wA.w + v[2]*wB.y + v[3]*wB.w
             + v[4]*wC.y + v[5]*wC.w + v[6]*wD.y + v[7]*wD.w;
    #pragma unroll
    for (int o = 16; o; o >>= 1) {
        a0 += __shfl_xor_sync(0xffffffffu, a0, o);
        a1 += __shfl_xor_sync(0xffffffffu, a1, o);
    }
    if (lane == 0) {
        out[2 * row]     = a0 + bout[0];
        out[2 * row + 1] = a1 + bout[1];
    }
}

// ---------------- streams + events ----------------
static cudaStream_t g_s2, g_s3;
static cudaEvent_t  g_evF, g_evZ, g_evD, g_evJ, g_evW;
namespace {
struct _HxInit {
    _HxInit() {
        cudaStreamCreateWithFlags(&g_s2, cudaStreamNonBlocking);
        cudaStreamCreateWithFlags(&g_s3, cudaStreamNonBlocking);
        cudaEventCreateWithFlags(&g_evF, cudaEventDisableTiming);
        cudaEventCreateWithFlags(&g_evZ, cudaEventDisableTiming);
        cudaEventCreateWithFlags(&g_evD, cudaEventDisableTiming);
        cudaEventCreateWithFlags(&g_evJ, cudaEventDisableTiming);
        cudaEventCreateWithFlags(&g_evW, cudaEventDisableTiming);
    }
};
static _HxInit _hx_init;
}

// ---------------- launch ----------------
extern "C" void kernel_launch(void* const* d_in, const int* in_sizes, int n_in,
                              void* d_out, int out_size) {
    const float* x    = (const float*)d_in[0];
    const int*   ei   = (const int*)  d_in[1];
    const float* fs   = (const float*)d_in[2];
    const float* fb   = (const float*)d_in[3];
    const float* bn0g = (const float*)d_in[4];
    const float* bn0b = (const float*)d_in[5];
    const float* W1   = (const float*)d_in[6];
    const float* b1   = (const float*)d_in[7];
    const float* bn1g = (const float*)d_in[8];
    const float* bn1b = (const float*)d_in[9];
    const float* ln1g = (const float*)d_in[10];
    const float* ln1b = (const float*)d_in[11];
    const float* W2   = (const float*)d_in[12];
    const float* b2   = (const float*)d_in[13];
    const float* bn2g = (const float*)d_in[14];
    const float* bn2b = (const float*)d_in[15];
    const float* ln2g = (const float*)d_in[16];
    const float* ln2b = (const float*)d_in[17];
    const float* Wout = (const float*)d_in[18];
    const float* bout = (const float*)d_in[19];
    float* out = (float*)d_out;

    const int* srcp = ei;
    const int* dstp = ei + EE;

    __half *p_hw, *p_h1, *p_h2;
    float *p_stats;
    cudaGetSymbolAddress((void**)&p_hw, g_hw);
    cudaGetSymbolAddress((void**)&p_h1, g_h1);
    cudaGetSymbolAddress((void**)&p_h2, g_h2);
    cudaGetSymbolAddress((void**)&p_stats, g_stats);
    __nv_bfloat16 *p_a2h, *p_a2l, *p_w1h, *p_w1l, *p_w2h, *p_w2l;
    cudaGetSymbolAddress((void**)&p_a2h, g_a2h);
    cudaGetSymbolAddress((void**)&p_a2l, g_a2l);
    cudaGetSymbolAddress((void**)&p_w1h, g_w1h);
    cudaGetSymbolAddress((void**)&p_w1l, g_w1l);
    cudaGetSymbolAddress((void**)&p_w2h, g_w2h);
    cudaGetSymbolAddress((void**)&p_w2l, g_w2l);

    const int G1_SMEM = 4 * 128 * 136 * 2;        // 139264
    const int G2_SMEM = 2 * 4 * 128 * 72 * 2;     // 147456
    cudaFuncSetAttribute(k_gemm1, cudaFuncAttributeMaxDynamicSharedMemorySize, G1_SMEM);
    cudaFuncSetAttribute(k_gemm2, cudaFuncAttributeMaxDynamicSharedMemorySize, G2_SMEM);

    const int WARP_GRID = (NN * 32 + 255) / 256;  // 6250
    const dim3 MGRID(2, (NN + 127) / 128);

    // ---- fork ----
    cudaEventRecord(g_evF, 0);
    cudaStreamWaitEvent(g_s2, g_evF, 0);
    cudaStreamWaitEvent(g_s3, g_evF, 0);

    // side stream 2: stats zero + graph preprocessing
    k_zero_all<<<6, 256, 0, g_s2>>>();
    cudaEventRecord(g_evZ, g_s2);
    k_zero_deg<<<(NN + 255) / 256, 256, 0, g_s2>>>();
    k_count<<<(EE + 255) / 256, 256, 0, g_s2>>>(dstp);
    k_dinv<<<(NN + 255) / 256, 256, 0, g_s2>>>();
    cudaEventRecord(g_evD, g_s2);
    k_scan1<<<NBLK, 1024, 0, g_s2>>>();
    k_scan2<<<1, 64, 0, g_s2>>>();
    k_scan3<<<(NN + 1023) / 1024, 1024, 0, g_s2>>>();
    k_scatter<<<(EE + 255) / 256, 256, 0, g_s2>>>(srcp, dstp);
    cudaEventRecord(g_evJ, g_s2);

    // side stream 3: weight prep
    k_prep_w<DIN><<<(HH * DIN + 255) / 256, 256, 0, g_s3>>>(W1, p_w1h, p_w1l);
    k_prep_w<HH><<<(HH * HH + 255) / 256, 256, 0, g_s3>>>(W2, p_w2h, p_w2l);
    cudaEventRecord(g_evW, g_s3);

    // ---- main stream ----
    cudaStreamWaitEvent(0, g_evZ, 0);
    k_colstats0<<<1024, DIN>>>(x, fs, fb);
    k_folde<<<1, HH>>>(fs, fb, bn0g, bn0b, W1);

    // layer 1 (BN0 folded into GEMM1)
    cudaStreamWaitEvent(0, g_evD, 0);
    cudaStreamWaitEvent(0, g_evW, 0);
    k_gemm1<<<MGRID, 256, G1_SMEM>>>(x, p_w1h, p_w1l, p_hw);
    cudaStreamWaitEvent(0, g_evJ, 0);
    k_aggregate<<<WARP_GRID, 256>>>(p_hw, b1, p_h1, p_stats + 512);
    k_bn_ln1<<<WARP_GRID, 256>>>(p_h1, p_stats + 512, bn1g, bn1b, ln1g, ln1b);

    // layer 2 (+ residual from splits, + fused output projection)
    k_gemm2<<<MGRID, 256, G2_SMEM>>>(p_a2h, p_a2l, p_w2h, p_w2l, p_hw);
    k_aggregate<<<WARP_GRID, 256>>>(p_hw, b2, p_h2, p_stats + 1024);
    k_bn_ln_out<<<WARP_GRID, 256>>>(p_h2, p_stats + 1024,
                                    bn2g, bn2b, ln2g, ln2b,
                                    Wout, bout, out);
}

// round 13
// speedup vs baseline: 1.3409x; 1.1462x over previous
#include <cuda_runtime.h>
#include <cuda_bf16.h>
#include <cuda_fp16.h>
#include <cstdint>
#include <cstddef>

#define NN  50000
#define EE  800000
#define DIN 128
#define HH  256
#define NBLK 49   // ceil(NN/1024)

// ---------------- static device scratch ----------------
__device__ __align__(16) __half g_hw[(size_t)NN * HH];     // GEMM output, dinv-scaled, fp16
__device__ __align__(16) __half g_h1[(size_t)NN * HH];     // agg1 output (fp16)
__device__ __align__(16) __half g_h2[(size_t)NN * HH];     // agg2 output (fp16)
__device__ __align__(16) __half g_a2[(size_t)NN * HH];     // post-LN h1 (fp16): GEMM2 A + residual
__device__ __align__(16) float g_stats[1536];
__device__ __align__(16) float g_s0[DIN];
__device__ __align__(16) float g_t0[DIN];
__device__ __align__(16) float g_e[HH];
__device__ float g_dinv[NN];
__device__ int   g_deg[NN];
__device__ int   g_off[NN + 1];
__device__ int   g_cur[NN];
__device__ int   g_esrc[EE];
__device__ int   g_bsum[NBLK];
__device__ int   g_bsumx[NBLK];
__device__ __align__(16) __nv_bfloat16 g_w1h[HH * DIN];
__device__ __align__(16) __nv_bfloat16 g_w1l[HH * DIN];
__device__ __align__(16) __half g_w2[HH * HH];             // W2^T fp16 [n][k]

// ---------------- helpers ----------------
__device__ __forceinline__ uint32_t smem_u32(const void* p) {
    uint32_t a;
    asm("{ .reg .u64 t; cvta.to.shared.u64 t, %1; cvt.u32.u64 %0, t; }" : "=r"(a) : "l"(p));
    return a;
}
__device__ __forceinline__ void ldm4(uint32_t* r, uint32_t addr) {
    asm volatile("ldmatrix.sync.aligned.m8n8.x4.shared.b16 {%0,%1,%2,%3}, [%4];"
                 : "=r"(r[0]), "=r"(r[1]), "=r"(r[2]), "=r"(r[3]) : "r"(addr));
}
__device__ __forceinline__ void mma16816(float* c, const uint32_t* a, const uint32_t* b) {
    asm volatile("mma.sync.aligned.m16n8k16.row.col.f32.bf16.bf16.f32 "
                 "{%0,%1,%2,%3}, {%4,%5,%6,%7}, {%8,%9}, {%0,%1,%2,%3};"
                 : "+f"(c[0]), "+f"(c[1]), "+f"(c[2]), "+f"(c[3])
                 : "r"(a[0]), "r"(a[1]), "r"(a[2]), "r"(a[3]), "r"(b[0]), "r"(b[1]));
}
__device__ __forceinline__ void mma16816h(float* c, const uint32_t* a, const uint32_t* b) {
    asm volatile("mma.sync.aligned.m16n8k16.row.col.f32.f16.f16.f32 "
                 "{%0,%1,%2,%3}, {%4,%5,%6,%7}, {%8,%9}, {%0,%1,%2,%3};"
                 : "+f"(c[0]), "+f"(c[1]), "+f"(c[2]), "+f"(c[3])
                 : "r"(a[0]), "r"(a[1]), "r"(a[2]), "r"(a[3]), "r"(b[0]), "r"(b[1]));
}
__device__ __forceinline__ void cpa16(uint32_t dst, const void* src, uint32_t vld) {
    asm volatile("cp.async.cg.shared.global [%0], [%1], 16, %2;"
                 :: "r"(dst), "l"(src), "r"(vld) : "memory");
}
#define CP_COMMIT() asm volatile("cp.async.commit_group;" ::: "memory")

__device__ __forceinline__ void ld8(float* o, const float* p, int lane) {
    float4 a = ((const float4*)p)[lane];
    float4 b = ((const float4*)p)[32 + lane];
    o[0]=a.x; o[1]=a.y; o[2]=a.z; o[3]=a.w;
    o[4]=b.x; o[5]=b.y; o[6]=b.z; o[7]=b.w;
}
__device__ __forceinline__ void st8(float* p, int lane, const float* v) {
    ((float4*)p)[lane]      = make_float4(v[0], v[1], v[2], v[3]);
    ((float4*)p)[32 + lane] = make_float4(v[4], v[5], v[6], v[7]);
}
__device__ __forceinline__ void ldh8(float* o, const __half* p, int lane) {
    uint2 a = __ldg((const uint2*)p + lane);
    uint2 b = __ldg((const uint2*)p + 32 + lane);
    float2 f;
    f = __half22float2(*(__half2*)&a.x); o[0]=f.x; o[1]=f.y;
    f = __half22float2(*(__half2*)&a.y); o[2]=f.x; o[3]=f.y;
    f = __half22float2(*(__half2*)&b.x); o[4]=f.x; o[5]=f.y;
    f = __half22float2(*(__half2*)&b.y); o[6]=f.x; o[7]=f.y;
}
__device__ __forceinline__ void sth8(__half* p, int lane, const float* v) {
    uint2 a, b;
    *(__half2*)&a.x = __floats2half2_rn(v[0], v[1]);
    *(__half2*)&a.y = __floats2half2_rn(v[2], v[3]);
    *(__half2*)&b.x = __floats2half2_rn(v[4], v[5]);
    *(__half2*)&b.y = __floats2half2_rn(v[6], v[7]);
    ((uint2*)p)[lane]      = a;
    ((uint2*)p)[32 + lane] = b;
}
__device__ __forceinline__ void split_bf16(float v, __nv_bfloat16& h, __nv_bfloat16& l) {
    h = __float2bfloat16_rn(v);
    l = __float2bfloat16_rn(v - __bfloat162float(h));
}
__device__ __forceinline__ void acc_edge(float* acc, const __half* hw, int s, int lane) {
    const uint2* rp = (const uint2*)(hw + (size_t)s * HH);
    uint2 a = __ldg(rp + lane);
    uint2 b = __ldg(rp + 32 + lane);
    float2 f;
    f = __half22float2(*(__half2*)&a.x); acc[0] += f.x; acc[1] += f.y;
    f = __half22float2(*(__half2*)&a.y); acc[2] += f.x; acc[3] += f.y;
    f = __half22float2(*(__half2*)&b.x); acc[4] += f.x; acc[5] += f.y;
    f = __half22float2(*(__half2*)&b.y); acc[6] += f.x; acc[7] += f.y;
}

// ---------------- graph preprocessing ----------------
__global__ void k_zero_all() {
    int i = blockIdx.x * blockDim.x + threadIdx.x;
    if (i < 1536) g_stats[i] = 0.0f;
}
__global__ void k_zero_deg() {
    int i = blockIdx.x * blockDim.x + threadIdx.x;
    if (i < NN) g_deg[i] = 0;
}
__global__ void k_count(const int* __restrict__ dst) {
    int e = blockIdx.x * blockDim.x + threadIdx.x;
    if (e < EE) atomicAdd(&g_deg[dst[e]], 1);
}
__global__ void k_dinv() {
    int i = blockIdx.x * blockDim.x + threadIdx.x;
    if (i < NN) g_dinv[i] = rsqrtf((float)g_deg[i] + 1.0f);
}
__global__ void k_scan1() {
    __shared__ int wsum[32];
    int i = blockIdx.x * 1024 + threadIdx.x;
    int lane = threadIdx.x & 31, w = threadIdx.x >> 5;
    int v = (i < NN) ? g_deg[i] : 0;
    int inc = v;
    #pragma unroll
    for (int o = 1; o < 32; o <<= 1) {
        int t = __shfl_up_sync(0xffffffffu, inc, o);
        if (lane >= o) inc += t;
    }
    if (lane == 31) wsum[w] = inc;
    __syncthreads();
    if (w == 0) {
        int s = wsum[lane];
        int si = s;
        #pragma unroll
        for (int o = 1; o < 32; o <<= 1) {
            int t = __shfl_up_sync(0xffffffffu, si, o);
            if (lane >= o) si += t;
        }
        wsum[lane] = si - s;
    }
    __syncthreads();
    int excl = wsum[w] + inc - v;
    if (i < NN) g_off[i] = excl;
    if (threadIdx.x == 1023) g_bsum[blockIdx.x] = excl + v;
}
__global__ void k_scan2() {
    __shared__ int sh[2];
    int t = threadIdx.x, lane = t & 31, w = t >> 5;
    int v = (t < NBLK) ? g_bsum[t] : 0;
    int inc = v;
    #pragma unroll
    for (int o = 1; o < 32; o <<= 1) {
        int x = __shfl_up_sync(0xffffffffu, inc, o);
        if (lane >= o) inc += x;
    }
    if (lane == 31) sh[w] = inc;
    __syncthreads();
    int add = (w == 1) ? sh[0] : 0;
    int excl = inc - v + add;
    if (t < NBLK) g_bsumx[t] = excl;
    if (t == NBLK - 1) g_off[NN] = excl + v;
}
__global__ void k_scan3() {
    int i = blockIdx.x * blockDim.x + threadIdx.x;
    if (i < NN) {
        int o = g_off[i] + g_bsumx[i >> 10];
        g_off[i] = o;
        g_cur[i] = o;
    }
}
__global__ void k_scatter(const int* __restrict__ src, const int* __restrict__ dst) {
    int e = blockIdx.x * blockDim.x + threadIdx.x;
    if (e >= EE) return;
    int p = atomicAdd(&g_cur[dst[e]], 1);
    g_esrc[p] = src[e];
}

// ---------------- weight prep ----------------
__global__ void k_prep_w1(const float* __restrict__ W,
                          __nv_bfloat16* __restrict__ oh, __nv_bfloat16* __restrict__ ol) {
    int i = blockIdx.x * blockDim.x + threadIdx.x;
    if (i >= HH * DIN) return;
    int n = i & (HH - 1), k = i >> 8;
    float v = W[k * HH + n];
    __nv_bfloat16 h, l;
    split_bf16(v, h, l);
    oh[n * DIN + k] = h;
    ol[n * DIN + k] = l;
}
__global__ void k_prep_w2(const float* __restrict__ W, __half* __restrict__ o) {
    int i = blockIdx.x * blockDim.x + threadIdx.x;
    if (i >= HH * HH) return;
    int n = i & (HH - 1), k = i >> 8;
    o[n * HH + k] = __float2half_rn(W[k * HH + n]);
}

// ---------------- BN0 fold ----------------
__global__ void k_colstats0(const float* __restrict__ A,
                            const float* __restrict__ fs, const float* __restrict__ fb) {
    int c = threadIdx.x;
    float scale = fs[c], bias = fb[c];
    float s = 0.0f, q = 0.0f;
    for (int r = blockIdx.x; r < NN; r += gridDim.x) {
        float v = A[(size_t)r * DIN + c] * scale + bias;
        s += v; q += v * v;
    }
    atomicAdd(&g_stats[c], s);
    atomicAdd(&g_stats[256 + c], q);
}
__global__ void k_folde(const float* __restrict__ fs, const float* __restrict__ fb,
                        const float* __restrict__ g,  const float* __restrict__ b,
                        const float* __restrict__ W1) {
    int t = threadIdx.x;
    if (t < DIN) {
        float mu  = g_stats[t] * (1.0f / NN);
        float var = g_stats[256 + t] * (1.0f / NN) - mu * mu;
        float a   = g[t] * rsqrtf(var + 1e-5f);
        g_s0[t] = fs[t] * a;
        g_t0[t] = (fb[t] - mu) * a + b[t];
    }
    __syncthreads();
    float e = 0.0f;
    #pragma unroll 8
    for (int k = 0; k < DIN; k++) e += g_t0[k] * W1[k * HH + t];
    g_e[t] = e;
}

// ---------------- GEMM1: bf16 3-pass, single-chunk K=128, folded BN0 ----------------
extern __shared__ char smraw[];

__global__ __launch_bounds__(256)
void k_gemm1(const float* __restrict__ X,
             const __nv_bfloat16* __restrict__ Bh, const __nv_bfloat16* __restrict__ Bl,
             __half* __restrict__ C) {
    constexpr int LDS = 136;
    char* smp = smraw;
    const uint32_t A_HI = 0, A_LO = 128u * LDS * 2, B_HI = 2u * 128 * LDS * 2, B_LO = 3u * 128 * LDS * 2;

    const int tid = threadIdx.x, lane = tid & 31, wid = tid >> 5;
    const int wm = wid >> 1, wn = wid & 1;
    const int row0 = blockIdx.y * 128;
    const int n0   = blockIdx.x * 128;
    const uint32_t smb = smem_u32(smp);

    #pragma unroll
    for (int it = 0; it < 8; it++) {
        int idx = tid + it * 256;
        int r = idx >> 4, q = idx & 15;
        size_t go = (size_t)(n0 + r) * DIN + q * 8;
        uint32_t so = (uint32_t)(r * LDS + q * 8) * 2;
        cpa16(smb + B_HI + so, Bh + go, 16u);
        cpa16(smb + B_LO + so, Bl + go, 16u);
    }
    CP_COMMIT();

    #pragma unroll
    for (int it = 0; it < 16; it++) {
        int idx = tid + it * 256;
        int r = idx >> 5, q = idx & 31;
        int gr = row0 + r;
        float4 v = make_float4(0.f, 0.f, 0.f, 0.f);
        if (gr < NN) v = ((const float4*)X)[(size_t)gr * 32 + q];
        float4 s4 = ((const float4*)g_s0)[q];
        v.x *= s4.x; v.y *= s4.y; v.z *= s4.z; v.w *= s4.w;
        __nv_bfloat16 h[4], l[4];
        split_bf16(v.x, h[0], l[0]); split_bf16(v.y, h[1], l[1]);
        split_bf16(v.z, h[2], l[2]); split_bf16(v.w, h[3], l[3]);
        uint32_t off = (uint32_t)(r * LDS + q * 4) * 2;
        *(uint2*)(smp + A_HI + off) = *(uint2*)h;
        *(uint2*)(smp + A_LO + off) = *(uint2*)l;
    }
    asm volatile("cp.async.wait_group 0;" ::: "memory");
    __syncthreads();

    float c[2][8][4] = {};
    const int a_row = wm * 32 + (lane & 15);
    const int a_kof = (lane >> 4) * 8;
    const int b_row = wn * 64 + ((lane >> 4) << 3) + (lane & 7);
    const int b_kof = ((lane >> 3) & 1) * 8;

    #pragma unroll
    for (int k16 = 0; k16 < 8; k16++) {
        uint32_t ah[2][4], al[2][4];
        #pragma unroll
        for (int mt = 0; mt < 2; mt++) {
            uint32_t ro = ((a_row + mt * 16) * LDS + k16 * 16 + a_kof) * 2;
            ldm4(ah[mt], smb + A_HI + ro);
            ldm4(al[mt], smb + A_LO + ro);
        }
        uint32_t bh[8][2], bl[8][2];
        #pragma unroll
        for (int p = 0; p < 4; p++) {
            uint32_t ro = ((b_row + p * 16) * LDS + k16 * 16 + b_kof) * 2;
            uint32_t r4[4];
            ldm4(r4, smb + B_HI + ro);
            bh[2*p][0]=r4[0]; bh[2*p][1]=r4[1]; bh[2*p+1][0]=r4[2]; bh[2*p+1][1]=r4[3];
            ldm4(r4, smb + B_LO + ro);
            bl[2*p][0]=r4[0]; bl[2*p][1]=r4[1]; bl[2*p+1][0]=r4[2]; bl[2*p+1][1]=r4[3];
        }
        #pragma unroll
        for (int mt = 0; mt < 2; mt++)
            #pragma unroll
            for (int nt = 0; nt < 8; nt++) {
                mma16816(c[mt][nt], ah[mt], bh[nt]);
                mma16816(c[mt][nt], al[mt], bh[nt]);
                mma16816(c[mt][nt], ah[mt], bl[nt]);
            }
    }

    const int g = lane >> 2, t = lane & 3;
    #pragma unroll
    for (int mt = 0; mt < 2; mt++) {
        int rbase = row0 + wm * 32 + mt * 16;
        int r1w = rbase + g, r2w = rbase + g + 8;
        float s1 = (r1w < NN) ? g_dinv[r1w] : 0.0f;
        float s2 = (r2w < NN) ? g_dinv[r2w] : 0.0f;
        #pragma unroll
        for (int nt = 0; nt < 8; nt++) {
            int col = n0 + wn * 64 + nt * 8 + 2 * t;
            float2 ev = *(const float2*)(g_e + col);
            if (r1w < NN)
                *(__half2*)(C + (size_t)r1w * HH + col) =
                    __floats2half2_rn((c[mt][nt][0] + ev.x) * s1, (c[mt][nt][1] + ev.y) * s1);
            if (r2w < NN)
                *(__half2*)(C + (size_t)r2w * HH + col) =
                    __floats2half2_rn((c[mt][nt][2] + ev.x) * s2, (c[mt][nt][3] + ev.y) * s2);
        }
    }
}

// ---------------- GEMM2: single-pass fp16, K=256, cp.async 2-stage ----------------
__global__ __launch_bounds__(256)
void k_gemm2(const __half* __restrict__ A, const __half* __restrict__ B,
             __half* __restrict__ C) {
    constexpr int K = HH, BK = 64, NCH = K / BK;
    constexpr int LDS = 72;
    constexpr int STG = 2 * 128 * LDS;   // halves per stage (A + B)

    const int tid = threadIdx.x, lane = tid & 31, wid = tid >> 5;
    const int wm = wid >> 1, wn = wid & 1;
    const int row0 = blockIdx.y * 128;
    const int n0   = blockIdx.x * 128;
    const uint32_t smb = smem_u32(smraw);

    float c[2][8][4] = {};

    const int a_row = wm * 32 + (lane & 15);
    const int a_kof = (lane >> 4) * 8;
    const int b_row = wn * 64 + ((lane >> 4) << 3) + (lane & 7);
    const int b_kof = ((lane >> 3) & 1) * 8;

    auto load_stage = [&](int ch, int buf) {
        const uint32_t sb = smb + (uint32_t)buf * STG * 2;
        #pragma unroll
        for (int it = 0; it < 4; it++) {
            int idx = tid + it * 256;
            int r = idx >> 3, q = idx & 7;
            int gr = row0 + r;
            uint32_t vld = (gr < NN) ? 16u : 0u;
            int grc = gr < NN ? gr : NN - 1;
            size_t go = (size_t)grc * K + ch * BK + q * 8;
            uint32_t so = (uint32_t)(r * LDS + q * 8) * 2;
            cpa16(sb + so, A + go, vld);
        }
        #pragma unroll
        for (int it = 0; it < 4; it++) {
            int idx = tid + it * 256;
            int r = idx >> 3, q = idx & 7;
            size_t go = (size_t)(n0 + r) * K + ch * BK + q * 8;
            uint32_t so = (uint32_t)(r * LDS + q * 8) * 2;
            cpa16(sb + 128 * LDS * 2 + so, B + go, 16u);
        }
        CP_COMMIT();
    };

    load_stage(0, 0);

    #pragma unroll
    for (int ch = 0; ch < NCH; ch++) {
        if (ch + 1 < NCH) {
            load_stage(ch + 1, (ch + 1) & 1);
            asm volatile("cp.async.wait_group 1;" ::: "memory");
        } else {
            asm volatile("cp.async.wait_group 0;" ::: "memory");
        }
        __syncthreads();

        const uint32_t sbase = smb + (uint32_t)(ch & 1) * STG * 2;
        #pragma unroll
        for (int k16 = 0; k16 < BK / 16; k16++) {
            uint32_t a[2][4];
            #pragma unroll
            for (int mt = 0; mt < 2; mt++)
                ldm4(a[mt], sbase + ((a_row + mt * 16) * LDS + k16 * 16 + a_kof) * 2);
            uint32_t b[8][2];
            #pragma unroll
            for (int p = 0; p < 4; p++) {
                uint32_t r4[4];
                ldm4(r4, sbase + 128 * LDS * 2 + ((b_row + p * 16) * LDS + k16 * 16 + b_kof) * 2);
                b[2*p][0] = r4[0]; b[2*p][1] = r4[1];
                b[2*p+1][0] = r4[2]; b[2*p+1][1] = r4[3];
            }
            #pragma unroll
            for (int mt = 0; mt < 2; mt++)
                #pragma unroll
                for (int nt = 0; nt < 8; nt++)
                    mma16816h(c[mt][nt], a[mt], b[nt]);
        }
        __syncthreads();
    }

    const int g = lane >> 2, t = lane & 3;
    #pragma unroll
    for (int mt = 0; mt < 2; mt++) {
        int rbase = row0 + wm * 32 + mt * 16;
        int r1w = rbase + g, r2w = rbase + g + 8;
        float s1 = (r1w < NN) ? g_dinv[r1w] : 0.0f;
        float s2 = (r2w < NN) ? g_dinv[r2w] : 0.0f;
        #pragma unroll
        for (int nt = 0; nt < 8; nt++) {
            int col = n0 + wn * 64 + nt * 8 + 2 * t;
            if (r1w < NN)
                *(__half2*)(C + (size_t)r1w * HH + col) =
                    __floats2half2_rn(c[mt][nt][0] * s1, c[mt][nt][1] * s1);
            if (r2w < NN)
                *(__half2*)(C + (size_t)r2w * HH + col) =
                    __floats2half2_rn(c[mt][nt][2] * s2, c[mt][nt][3] * s2);
        }
    }
}

// ---------------- GCN aggregation (fp16 in/out) + fused BN column stats ----------
__global__ __launch_bounds__(256)
void k_aggregate(const __half* __restrict__ hw, const float* __restrict__ bias,
                 __half* __restrict__ out, float* __restrict__ stats) {
    __shared__ float red[8][256];
    int d    = (blockIdx.x * blockDim.x + threadIdx.x) >> 5;
    int lane = threadIdx.x & 31;
    int wid  = threadIdx.x >> 5;

    float acc[8] = {};
    const int beg = g_off[d], end = g_off[d + 1];

    int p0 = beg;
    while (p0 < end) {
        int cnt = end - p0;
        if (cnt > 32) cnt = 32;
        int idxv = (lane < cnt) ? g_esrc[p0 + lane] : 0;
        int j = 0;
        for (; j + 4 <= cnt; j += 4) {
            int s0 = __shfl_sync(0xffffffffu, idxv, j);
            int s1 = __shfl_sync(0xffffffffu, idxv, j + 1);
            int s2 = __shfl_sync(0xffffffffu, idxv, j + 2);
            int s3 = __shfl_sync(0xffffffffu, idxv, j + 3);
            acc_edge(acc, hw, s0, lane);
            acc_edge(acc, hw, s1, lane);
            acc_edge(acc, hw, s2, lane);
            acc_edge(acc, hw, s3, lane);
        }
        for (; j < cnt; j++) {
            int s0 = __shfl_sync(0xffffffffu, idxv, j);
            acc_edge(acc, hw, s0, lane);
        }
        p0 += cnt;
    }

    float di = g_dinv[d];
    float sv[8], bv[8], r[8];
    ldh8(sv, hw + (size_t)d * HH, lane);
    ld8(bv, bias, lane);
    #pragma unroll
    for (int i = 0; i < 8; i++)
        r[i] = fmaxf(di * (acc[i] + sv[i]) + bv[i], 0.0f);
    sth8(out + (size_t)d * HH, lane, r);

    st8(&red[wid][0], lane, r);
    __syncthreads();
    int cidx = threadIdx.x;
    float s = 0.f, q = 0.f;
    #pragma unroll
    for (int w = 0; w < 8; w++) {
        float v = red[w][cidx];
        s += v; q += v * v;
    }
    atomicAdd(&stats[cidx], s);
    atomicAdd(&stats[256 + cidx], q);
}

// ---------------- BN -> LN -> fp16 store (layer 1) ----------------
__global__ __launch_bounds__(256)
void k_bn_ln1(const __half* __restrict__ t, const float* __restrict__ stats,
              const float* __restrict__ bng, const float* __restrict__ bnb,
              const float* __restrict__ lng, const float* __restrict__ lnb) {
    int row  = (blockIdx.x * blockDim.x + threadIdx.x) >> 5;
    int lane = threadIdx.x & 31;
    if (row >= NN) return;

    float v[8], s[8], q[8], g[8], b[8];
    ldh8(v, t + (size_t)row * HH, lane);
    ld8(s, stats, lane);
    ld8(q, stats + 256, lane);
    ld8(g, bng, lane);
    ld8(b, bnb, lane);

    #pragma unroll
    for (int i = 0; i < 8; i++) {
        float mu  = s[i] * (1.0f / NN);
        float var = q[i] * (1.0f / NN) - mu * mu;
        v[i] = g[i] * (v[i] - mu) * rsqrtf(var + 1e-5f) + b[i];
    }

    float sum = 0.f;
    #pragma unroll
    for (int i = 0; i < 8; i++) sum += v[i];
    #pragma unroll
    for (int o = 16; o; o >>= 1) sum += __shfl_xor_sync(0xffffffffu, sum, o);
    float mu = sum * (1.0f / HH);

    float ss = 0.f;
    #pragma unroll
    for (int i = 0; i < 8; i++) { float dd = v[i] - mu; ss += dd * dd; }
    #pragma unroll
    for (int o = 16; o; o >>= 1) ss += __shfl_xor_sync(0xffffffffu, ss, o);
    float rs = rsqrtf(ss * (1.0f / HH) + 1e-5f);

    ld8(g, lng, lane);
    ld8(b, lnb, lane);
    #pragma unroll
    for (int i = 0; i < 8; i++) v[i] = g[i] * (v[i] - mu) * rs + b[i];

    sth8(g_a2 + (size_t)row * HH, lane, v);
}

// ---------------- final: BN -> LN -> +residual(fp16) -> out-proj ----------------
__global__ __launch_bounds__(256)
void k_bn_ln_out(const __half* __restrict__ t, const float* __restrict__ stats,
                 const float* __restrict__ bng, const float* __restrict__ bnb,
                 const float* __restrict__ lng, const float* __restrict__ lnb,
                 const float* __restrict__ Wout, const float* __restrict__ bout,
                 float* __restrict__ out) {
    int row  = (blockIdx.x * blockDim.x + threadIdx.x) >> 5;
    int lane = threadIdx.x & 31;
    if (row >= NN) return;

    float v[8], s[8], q[8], g[8], b[8];
    ldh8(v, t + (size_t)row * HH, lane);
    ld8(s, stats, lane);
    ld8(q, stats + 256, lane);
    ld8(g, bng, lane);
    ld8(b, bnb, lane);

    #pragma unroll
    for (int i = 0; i < 8; i++) {
        float mu  = s[i] * (1.0f / NN);
        float var = q[i] * (1.0f / NN) - mu * mu;
        v[i] = g[i] * (v[i] - mu) * rsqrtf(var + 1e-5f) + b[i];
    }

    float sum = 0.f;
    #pragma unroll
    for (int i = 0; i < 8; i++) sum += v[i];
    #pragma unroll
    for (int o = 16; o; o >>= 1) sum += __shfl_xor_sync(0xffffffffu, sum, o);
    float mu = sum * (1.0f / HH);

    float ss = 0.f;
    #pragma unroll
    for (int i = 0; i < 8; i++) { float dd = v[i] - mu; ss += dd * dd; }
    #pragma unroll
    for (int o = 16; o; o >>= 1) ss += __shfl_xor_sync(0xffffffffu, ss, o);
    float rs = rsqrtf(ss * (1.0f / HH) + 1e-5f);

    ld8(g, lng, lane);
    ld8(b, lnb, lane);
    float r[8];
    ldh8(r, g_a2 + (size_t)row * HH, lane);
    #pragma unroll
    for (int i = 0; i < 8; i++) v[i] = g[i] * (v[i] - mu) * rs + b[i] + r[i];

    const float4* W4 = (const float4*)Wout;
    float4 wA = W4[2 * lane],      wB = W4[2 * lane + 1];
    float4 wC = W4[64 + 2 * lane], wD = W4[65 + 2 * lane];
    float a0 = v[0]*wA.x + v[1]*wA.z + v[2]*wB.x + v[3]*wB.z
             + v[4]*wC.x + v[5]*wC.z + v[6]*wD.x + v[7]*wD.z;
    float a1 = v[0]*wA.y + v[1]*wA.w + v[2]*wB.y + v[3]*wB.w
             + v[4]*wC.y + v[5]*wC.w + v[6]*wD.y + v[7]*wD.w;
    #pragma unroll
    for (int o = 16; o; o >>= 1) {
        a0 += __shfl_xor_sync(0xffffffffu, a0, o);
        a1 += __shfl_xor_sync(0xffffffffu, a1, o);
    }
    if (lane == 0) {
        out[2 * row]     = a0 + bout[0];
        out[2 * row + 1] = a1 + bout[1];
    }
}

// ---------------- streams + events ----------------
static cudaStream_t g_s2, g_s3;
static cudaEvent_t  g_evF, g_evZ, g_evD, g_evJ, g_evW;
namespace {
struct _HxInit {
    _HxInit() {
        cudaStreamCreateWithFlags(&g_s2, cudaStreamNonBlocking);
        cudaStreamCreateWithFlags(&g_s3, cudaStreamNonBlocking);
        cudaEventCreateWithFlags(&g_evF, cudaEventDisableTiming);
        cudaEventCreateWithFlags(&g_evZ, cudaEventDisableTiming);
        cudaEventCreateWithFlags(&g_evD, cudaEventDisableTiming);
        cudaEventCreateWithFlags(&g_evJ, cudaEventDisableTiming);
        cudaEventCreateWithFlags(&g_evW, cudaEventDisableTiming);
    }
};
static _HxInit _hx_init;
}

// ---------------- launch ----------------
extern "C" void kernel_launch(void* const* d_in, const int* in_sizes, int n_in,
                              void* d_out, int out_size) {
    const float* x    = (const float*)d_in[0];
    const int*   ei   = (const int*)  d_in[1];
    const float* fs   = (const float*)d_in[2];
    const float* fb   = (const float*)d_in[3];
    const float* bn0g = (const float*)d_in[4];
    const float* bn0b = (const float*)d_in[5];
    const float* W1   = (const float*)d_in[6];
    const float* b1   = (const float*)d_in[7];
    const float* bn1g = (const float*)d_in[8];
    const float* bn1b = (const float*)d_in[9];
    const float* ln1g = (const float*)d_in[10];
    const float* ln1b = (const float*)d_in[11];
    const float* W2   = (const float*)d_in[12];
    const float* b2   = (const float*)d_in[13];
    const float* bn2g = (const float*)d_in[14];
    const float* bn2b = (const float*)d_in[15];
    const float* ln2g = (const float*)d_in[16];
    const float* ln2b = (const float*)d_in[17];
    const float* Wout = (const float*)d_in[18];
    const float* bout = (const float*)d_in[19];
    float* out = (float*)d_out;

    const int* srcp = ei;
    const int* dstp = ei + EE;

    __half *p_hw, *p_h1, *p_h2, *p_a2, *p_w2;
    float *p_stats;
    cudaGetSymbolAddress((void**)&p_hw, g_hw);
    cudaGetSymbolAddress((void**)&p_h1, g_h1);
    cudaGetSymbolAddress((void**)&p_h2, g_h2);
    cudaGetSymbolAddress((void**)&p_a2, g_a2);
    cudaGetSymbolAddress((void**)&p_w2, g_w2);
    cudaGetSymbolAddress((void**)&p_stats, g_stats);
    __nv_bfloat16 *p_w1h, *p_w1l;
    cudaGetSymbolAddress((void**)&p_w1h, g_w1h);
    cudaGetSymbolAddress((void**)&p_w1l, g_w1l);

    const int G1_SMEM = 4 * 128 * 136 * 2;        // 139264
    const int G2_SMEM = 2 * 2 * 128 * 72 * 2;     // 73728
    cudaFuncSetAttribute(k_gemm1, cudaFuncAttributeMaxDynamicSharedMemorySize, G1_SMEM);
    cudaFuncSetAttribute(k_gemm2, cudaFuncAttributeMaxDynamicSharedMemorySize, G2_SMEM);

    const int WARP_GRID = (NN * 32 + 255) / 256;  // 6250
    const dim3 MGRID(2, (NN + 127) / 128);

    // ---- fork ----
    cudaEventRecord(g_evF, 0);
    cudaStreamWaitEvent(g_s2, g_evF, 0);
    cudaStreamWaitEvent(g_s3, g_evF, 0);

    // side stream 2: stats zero + graph preprocessing
    k_zero_all<<<6, 256, 0, g_s2>>>();
    cudaEventRecord(g_evZ, g_s2);
    k_zero_deg<<<(NN + 255) / 256, 256, 0, g_s2>>>();
    k_count<<<(EE + 255) / 256, 256, 0, g_s2>>>(dstp);
    k_dinv<<<(NN + 255) / 256, 256, 0, g_s2>>>();
    cudaEventRecord(g_evD, g_s2);
    k_scan1<<<NBLK, 1024, 0, g_s2>>>();
    k_scan2<<<1, 64, 0, g_s2>>>();
    k_scan3<<<(NN + 1023) / 1024, 1024, 0, g_s2>>>();
    k_scatter<<<(EE + 255) / 256, 256, 0, g_s2>>>(srcp, dstp);
    cudaEventRecord(g_evJ, g_s2);

    // side stream 3: weight prep
    k_prep_w1<<<(HH * DIN + 255) / 256, 256, 0, g_s3>>>(W1, p_w1h, p_w1l);
    k_prep_w2<<<(HH * HH + 255) / 256, 256, 0, g_s3>>>(W2, p_w2);
    cudaEventRecord(g_evW, g_s3);

    // ---- main stream ----
    cudaStreamWaitEvent(0, g_evZ, 0);
    k_colstats0<<<1024, DIN>>>(x, fs, fb);
    k_folde<<<1, HH>>>(fs, fb, bn0g, bn0b, W1);

    // layer 1 (BN0 folded into GEMM1)
    cudaStreamWaitEvent(0, g_evD, 0);
    cudaStreamWaitEvent(0, g_evW, 0);
    k_gemm1<<<MGRID, 256, G1_SMEM>>>(x, p_w1h, p_w1l, p_hw);
    cudaStreamWaitEvent(0, g_evJ, 0);
    k_aggregate<<<WARP_GRID, 256>>>(p_hw, b1, p_h1, p_stats + 512);
    k_bn_ln1<<<WARP_GRID, 256>>>(p_h1, p_stats + 512, bn1g, bn1b, ln1g, ln1b);

    // layer 2 (single-pass fp16 GEMM, residual from g_a2, fused out-proj)
    k_gemm2<<<MGRID, 256, G2_SMEM>>>(p_a2, p_w2, p_hw);
    k_aggregate<<<WARP_GRID, 256>>>(p_hw, b2, p_h2, p_stats + 1024);
    k_bn_ln_out<<<WARP_GRID, 256>>>(p_h2, p_stats + 1024,
                                    bn2g, bn2b, ln2g, ln2b,
                                    Wout, bout, out);
}

// round 14
// speedup vs baseline: 1.4401x; 1.0740x over previous
#include <cuda_runtime.h>
#include <cuda_bf16.h>
#include <cuda_fp16.h>
#include <cstdint>
#include <cstddef>

#define NN  50000
#define EE  800000
#define DIN 128
#define HH  256
#define NBLK 49   // ceil(NN/1024)

// ---------------- static device scratch ----------------
__device__ __align__(16) __half g_hw[(size_t)NN * HH];     // GEMM output, dinv-scaled, fp16
__device__ __align__(16) __half g_h1[(size_t)NN * HH];     // agg1 output (fp16)
__device__ __align__(16) __half g_h2[(size_t)NN * HH];     // agg2 output (fp16)
__device__ __align__(16) __half g_a2[(size_t)NN * HH];     // post-LN h1 (fp16): GEMM2 A + residual
__device__ __align__(16) float g_stats[1536];
__device__ __align__(16) float g_s0[DIN];
__device__ __align__(16) float g_t0[DIN];
__device__ __align__(16) float g_e[HH];
__device__ float g_dinv[NN];
__device__ int   g_deg[NN];
__device__ int   g_off[NN + 1];
__device__ int   g_cur[NN];
__device__ int   g_esrc[EE];
__device__ int   g_bsum[NBLK];
__device__ int   g_bsumx[NBLK];
__device__ __align__(16) __half g_w1[HH * DIN];            // W1^T fp16 [n][k]
__device__ __align__(16) __half g_w2[HH * HH];             // W2^T fp16 [n][k]

// ---------------- helpers ----------------
__device__ __forceinline__ uint32_t smem_u32(const void* p) {
    uint32_t a;
    asm("{ .reg .u64 t; cvta.to.shared.u64 t, %1; cvt.u32.u64 %0, t; }" : "=r"(a) : "l"(p));
    return a;
}
__device__ __forceinline__ void ldm4(uint32_t* r, uint32_t addr) {
    asm volatile("ldmatrix.sync.aligned.m8n8.x4.shared.b16 {%0,%1,%2,%3}, [%4];"
                 : "=r"(r[0]), "=r"(r[1]), "=r"(r[2]), "=r"(r[3]) : "r"(addr));
}
__device__ __forceinline__ void mma16816h(float* c, const uint32_t* a, const uint32_t* b) {
    asm volatile("mma.sync.aligned.m16n8k16.row.col.f32.f16.f16.f32 "
                 "{%0,%1,%2,%3}, {%4,%5,%6,%7}, {%8,%9}, {%0,%1,%2,%3};"
                 : "+f"(c[0]), "+f"(c[1]), "+f"(c[2]), "+f"(c[3])
                 : "r"(a[0]), "r"(a[1]), "r"(a[2]), "r"(a[3]), "r"(b[0]), "r"(b[1]));
}
__device__ __forceinline__ void cpa16(uint32_t dst, const void* src, uint32_t vld) {
    asm volatile("cp.async.cg.shared.global [%0], [%1], 16, %2;"
                 :: "r"(dst), "l"(src), "r"(vld) : "memory");
}
#define CP_COMMIT() asm volatile("cp.async.commit_group;" ::: "memory")

__device__ __forceinline__ void ld8(float* o, const float* p, int lane) {
    float4 a = ((const float4*)p)[lane];
    float4 b = ((const float4*)p)[32 + lane];
    o[0]=a.x; o[1]=a.y; o[2]=a.z; o[3]=a.w;
    o[4]=b.x; o[5]=b.y; o[6]=b.z; o[7]=b.w;
}
__device__ __forceinline__ void st8(float* p, int lane, const float* v) {
    ((float4*)p)[lane]      = make_float4(v[0], v[1], v[2], v[3]);
    ((float4*)p)[32 + lane] = make_float4(v[4], v[5], v[6], v[7]);
}
__device__ __forceinline__ void ldh8(float* o, const __half* p, int lane) {
    uint2 a = __ldg((const uint2*)p + lane);
    uint2 b = __ldg((const uint2*)p + 32 + lane);
    float2 f;
    f = __half22float2(*(__half2*)&a.x); o[0]=f.x; o[1]=f.y;
    f = __half22float2(*(__half2*)&a.y); o[2]=f.x; o[3]=f.y;
    f = __half22float2(*(__half2*)&b.x); o[4]=f.x; o[5]=f.y;
    f = __half22float2(*(__half2*)&b.y); o[6]=f.x; o[7]=f.y;
}
__device__ __forceinline__ void sth8(__half* p, int lane, const float* v) {
    uint2 a, b;
    *(__half2*)&a.x = __floats2half2_rn(v[0], v[1]);
    *(__half2*)&a.y = __floats2half2_rn(v[2], v[3]);
    *(__half2*)&b.x = __floats2half2_rn(v[4], v[5]);
    *(__half2*)&b.y = __floats2half2_rn(v[6], v[7]);
    ((uint2*)p)[lane]      = a;
    ((uint2*)p)[32 + lane] = b;
}
__device__ __forceinline__ void acc_edge(float* acc, const __half* hw, int s, int lane) {
    const uint2* rp = (const uint2*)(hw + (size_t)s * HH);
    uint2 a = __ldg(rp + lane);
    uint2 b = __ldg(rp + 32 + lane);
    float2 f;
    f = __half22float2(*(__half2*)&a.x); acc[0] += f.x; acc[1] += f.y;
    f = __half22float2(*(__half2*)&a.y); acc[2] += f.x; acc[3] += f.y;
    f = __half22float2(*(__half2*)&b.x); acc[4] += f.x; acc[5] += f.y;
    f = __half22float2(*(__half2*)&b.y); acc[6] += f.x; acc[7] += f.y;
}

// ---------------- graph preprocessing ----------------
__global__ void k_zero_all() {
    int i = blockIdx.x * blockDim.x + threadIdx.x;
    if (i < 1536) g_stats[i] = 0.0f;
}
__global__ void k_zero_deg() {
    int i = blockIdx.x * blockDim.x + threadIdx.x;
    if (i < NN) g_deg[i] = 0;
}
__global__ void k_count(const int* __restrict__ dst) {
    int e = blockIdx.x * blockDim.x + threadIdx.x;
    if (e < EE) atomicAdd(&g_deg[dst[e]], 1);
}
__global__ void k_dinv() {
    int i = blockIdx.x * blockDim.x + threadIdx.x;
    if (i < NN) g_dinv[i] = rsqrtf((float)g_deg[i] + 1.0f);
}
__global__ void k_scan1() {
    __shared__ int wsum[32];
    int i = blockIdx.x * 1024 + threadIdx.x;
    int lane = threadIdx.x & 31, w = threadIdx.x >> 5;
    int v = (i < NN) ? g_deg[i] : 0;
    int inc = v;
    #pragma unroll
    for (int o = 1; o < 32; o <<= 1) {
        int t = __shfl_up_sync(0xffffffffu, inc, o);
        if (lane >= o) inc += t;
    }
    if (lane == 31) wsum[w] = inc;
    __syncthreads();
    if (w == 0) {
        int s = wsum[lane];
        int si = s;
        #pragma unroll
        for (int o = 1; o < 32; o <<= 1) {
            int t = __shfl_up_sync(0xffffffffu, si, o);
            if (lane >= o) si += t;
        }
        wsum[lane] = si - s;
    }
    __syncthreads();
    int excl = wsum[w] + inc - v;
    if (i < NN) g_off[i] = excl;
    if (threadIdx.x == 1023) g_bsum[blockIdx.x] = excl + v;
}
__global__ void k_scan2() {
    __shared__ int sh[2];
    int t = threadIdx.x, lane = t & 31, w = t >> 5;
    int v = (t < NBLK) ? g_bsum[t] : 0;
    int inc = v;
    #pragma unroll
    for (int o = 1; o < 32; o <<= 1) {
        int x = __shfl_up_sync(0xffffffffu, inc, o);
        if (lane >= o) inc += x;
    }
    if (lane == 31) sh[w] = inc;
    __syncthreads();
    int add = (w == 1) ? sh[0] : 0;
    int excl = inc - v + add;
    if (t < NBLK) g_bsumx[t] = excl;
    if (t == NBLK - 1) g_off[NN] = excl + v;
}
__global__ void k_scan3() {
    int i = blockIdx.x * blockDim.x + threadIdx.x;
    if (i < NN) {
        int o = g_off[i] + g_bsumx[i >> 10];
        g_off[i] = o;
        g_cur[i] = o;
    }
}
__global__ void k_scatter(const int* __restrict__ src, const int* __restrict__ dst) {
    int e = blockIdx.x * blockDim.x + threadIdx.x;
    if (e >= EE) return;
    int p = atomicAdd(&g_cur[dst[e]], 1);
    g_esrc[p] = src[e];
}

// ---------------- weight prep (fp16 transposed) ----------------
template <int K>
__global__ void k_prep_w(const float* __restrict__ W, __half* __restrict__ o) {
    int i = blockIdx.x * blockDim.x + threadIdx.x;
    if (i >= HH * K) return;
    int n = i & (HH - 1), k = i >> 8;
    o[n * K + k] = __float2half_rn(W[k * HH + n]);
}

// ---------------- BN0 fold ----------------
__global__ void k_colstats0(const float* __restrict__ A,
                            const float* __restrict__ fs, const float* __restrict__ fb) {
    int c = threadIdx.x;
    float scale = fs[c], bias = fb[c];
    float s = 0.0f, q = 0.0f;
    for (int r = blockIdx.x; r < NN; r += gridDim.x) {
        float v = A[(size_t)r * DIN + c] * scale + bias;
        s += v; q += v * v;
    }
    atomicAdd(&g_stats[c], s);
    atomicAdd(&g_stats[256 + c], q);
}
__global__ void k_folde(const float* __restrict__ fs, const float* __restrict__ fb,
                        const float* __restrict__ g,  const float* __restrict__ b,
                        const float* __restrict__ W1) {
    int t = threadIdx.x;
    if (t < DIN) {
        float mu  = g_stats[t] * (1.0f / NN);
        float var = g_stats[256 + t] * (1.0f / NN) - mu * mu;
        float a   = g[t] * rsqrtf(var + 1e-5f);
        g_s0[t] = fs[t] * a;
        g_t0[t] = (fb[t] - mu) * a + b[t];
    }
    __syncthreads();
    float e = 0.0f;
    #pragma unroll 8
    for (int k = 0; k < DIN; k++) e += g_t0[k] * W1[k * HH + t];
    g_e[t] = e;
}

extern __shared__ char smraw[];

// ---------------- GEMM1: single-pass fp16, K=128, folded BN0 ----------------
__global__ __launch_bounds__(256)
void k_gemm1(const float* __restrict__ X, const __half* __restrict__ B,
             __half* __restrict__ C) {
    constexpr int LDS = 136;
    char* smp = smraw;
    const uint32_t A_OFF = 0, B_OFF = 128u * LDS * 2;

    const int tid = threadIdx.x, lane = tid & 31, wid = tid >> 5;
    const int wm = wid >> 1, wn = wid & 1;
    const int row0 = blockIdx.y * 128;
    const int n0   = blockIdx.x * 128;
    const uint32_t smb = smem_u32(smp);

    // B via cp.async: 128 rows x 128 halves
    #pragma unroll
    for (int it = 0; it < 8; it++) {
        int idx = tid + it * 256;
        int r = idx >> 4, q = idx & 15;
        size_t go = (size_t)(n0 + r) * DIN + q * 8;
        cpa16(smb + B_OFF + (uint32_t)(r * LDS + q * 8) * 2, B + go, 16u);
    }
    CP_COMMIT();

    // A: fp32 x, scale by s0, convert fp16
    #pragma unroll
    for (int it = 0; it < 16; it++) {
        int idx = tid + it * 256;
        int r = idx >> 5, q = idx & 31;
        int gr = row0 + r;
        float4 v = make_float4(0.f, 0.f, 0.f, 0.f);
        if (gr < NN) v = ((const float4*)X)[(size_t)gr * 32 + q];
        float4 s4 = ((const float4*)g_s0)[q];
        __half h[4];
        h[0] = __float2half_rn(v.x * s4.x);
        h[1] = __float2half_rn(v.y * s4.y);
        h[2] = __float2half_rn(v.z * s4.z);
        h[3] = __float2half_rn(v.w * s4.w);
        *(uint2*)(smp + A_OFF + (uint32_t)(r * LDS + q * 4) * 2) = *(uint2*)h;
    }
    asm volatile("cp.async.wait_group 0;" ::: "memory");
    __syncthreads();

    float c[2][8][4] = {};
    const int a_row = wm * 32 + (lane & 15);
    const int a_kof = (lane >> 4) * 8;
    const int b_row = wn * 64 + ((lane >> 4) << 3) + (lane & 7);
    const int b_kof = ((lane >> 3) & 1) * 8;

    #pragma unroll
    for (int k16 = 0; k16 < 8; k16++) {
        uint32_t a[2][4];
        #pragma unroll
        for (int mt = 0; mt < 2; mt++)
            ldm4(a[mt], smb + A_OFF + ((a_row + mt * 16) * LDS + k16 * 16 + a_kof) * 2);
        uint32_t b[8][2];
        #pragma unroll
        for (int p = 0; p < 4; p++) {
            uint32_t r4[4];
            ldm4(r4, smb + B_OFF + ((b_row + p * 16) * LDS + k16 * 16 + b_kof) * 2);
            b[2*p][0] = r4[0]; b[2*p][1] = r4[1];
            b[2*p+1][0] = r4[2]; b[2*p+1][1] = r4[3];
        }
        #pragma unroll
        for (int mt = 0; mt < 2; mt++)
            #pragma unroll
            for (int nt = 0; nt < 8; nt++)
                mma16816h(c[mt][nt], a[mt], b[nt]);
    }

    const int g = lane >> 2, t = lane & 3;
    #pragma unroll
    for (int mt = 0; mt < 2; mt++) {
        int rbase = row0 + wm * 32 + mt * 16;
        int r1w = rbase + g, r2w = rbase + g + 8;
        float s1 = (r1w < NN) ? g_dinv[r1w] : 0.0f;
        float s2 = (r2w < NN) ? g_dinv[r2w] : 0.0f;
        #pragma unroll
        for (int nt = 0; nt < 8; nt++) {
            int col = n0 + wn * 64 + nt * 8 + 2 * t;
            float2 ev = *(const float2*)(g_e + col);
            if (r1w < NN)
                *(__half2*)(C + (size_t)r1w * HH + col) =
                    __floats2half2_rn((c[mt][nt][0] + ev.x) * s1, (c[mt][nt][1] + ev.y) * s1);
            if (r2w < NN)
                *(__half2*)(C + (size_t)r2w * HH + col) =
                    __floats2half2_rn((c[mt][nt][2] + ev.x) * s2, (c[mt][nt][3] + ev.y) * s2);
        }
    }
}

// ---------------- GEMM2: single-pass fp16, K=256, cp.async 2-stage ----------------
__global__ __launch_bounds__(256)
void k_gemm2(const __half* __restrict__ A, const __half* __restrict__ B,
             __half* __restrict__ C) {
    constexpr int K = HH, BK = 64, NCH = K / BK;
    constexpr int LDS = 72;
    constexpr int STG = 2 * 128 * LDS;

    const int tid = threadIdx.x, lane = tid & 31, wid = tid >> 5;
    const int wm = wid >> 1, wn = wid & 1;
    const int row0 = blockIdx.y * 128;
    const int n0   = blockIdx.x * 128;
    const uint32_t smb = smem_u32(smraw);

    float c[2][8][4] = {};

    const int a_row = wm * 32 + (lane & 15);
    const int a_kof = (lane >> 4) * 8;
    const int b_row = wn * 64 + ((lane >> 4) << 3) + (lane & 7);
    const int b_kof = ((lane >> 3) & 1) * 8;

    auto load_stage = [&](int ch, int buf) {
        const uint32_t sb = smb + (uint32_t)buf * STG * 2;
        #pragma unroll
        for (int it = 0; it < 4; it++) {
            int idx = tid + it * 256;
            int r = idx >> 3, q = idx & 7;
            int gr = row0 + r;
            uint32_t vld = (gr < NN) ? 16u : 0u;
            int grc = gr < NN ? gr : NN - 1;
            size_t go = (size_t)grc * K + ch * BK + q * 8;
            cpa16(sb + (uint32_t)(r * LDS + q * 8) * 2, A + go, vld);
        }
        #pragma unroll
        for (int it = 0; it < 4; it++) {
            int idx = tid + it * 256;
            int r = idx >> 3, q = idx & 7;
            size_t go = (size_t)(n0 + r) * K + ch * BK + q * 8;
            cpa16(sb + 128 * LDS * 2 + (uint32_t)(r * LDS + q * 8) * 2, B + go, 16u);
        }
        CP_COMMIT();
    };

    load_stage(0, 0);

    #pragma unroll
    for (int ch = 0; ch < NCH; ch++) {
        if (ch + 1 < NCH) {
            load_stage(ch + 1, (ch + 1) & 1);
            asm volatile("cp.async.wait_group 1;" ::: "memory");
        } else {
            asm volatile("cp.async.wait_group 0;" ::: "memory");
        }
        __syncthreads();

        const uint32_t sbase = smb + (uint32_t)(ch & 1) * STG * 2;
        #pragma unroll
        for (int k16 = 0; k16 < BK / 16; k16++) {
            uint32_t a[2][4];
            #pragma unroll
            for (int mt = 0; mt < 2; mt++)
                ldm4(a[mt], sbase + ((a_row + mt * 16) * LDS + k16 * 16 + a_kof) * 2);
            uint32_t b[8][2];
            #pragma unroll
            for (int p = 0; p < 4; p++) {
                uint32_t r4[4];
                ldm4(r4, sbase + 128 * LDS * 2 + ((b_row + p * 16) * LDS + k16 * 16 + b_kof) * 2);
                b[2*p][0] = r4[0]; b[2*p][1] = r4[1];
                b[2*p+1][0] = r4[2]; b[2*p+1][1] = r4[3];
            }
            #pragma unroll
            for (int mt = 0; mt < 2; mt++)
                #pragma unroll
                for (int nt = 0; nt < 8; nt++)
                    mma16816h(c[mt][nt], a[mt], b[nt]);
        }
        __syncthreads();
    }

    const int g = lane >> 2, t = lane & 3;
    #pragma unroll
    for (int mt = 0; mt < 2; mt++) {
        int rbase = row0 + wm * 32 + mt * 16;
        int r1w = rbase + g, r2w = rbase + g + 8;
        float s1 = (r1w < NN) ? g_dinv[r1w] : 0.0f;
        float s2 = (r2w < NN) ? g_dinv[r2w] : 0.0f;
        #pragma unroll
        for (int nt = 0; nt < 8; nt++) {
            int col = n0 + wn * 64 + nt * 8 + 2 * t;
            if (r1w < NN)
                *(__half2*)(C + (size_t)r1w * HH + col) =
                    __floats2half2_rn(c[mt][nt][0] * s1, c[mt][nt][1] * s1);
            if (r2w < NN)
                *(__half2*)(C + (size_t)r2w * HH + col) =
                    __floats2half2_rn(c[mt][nt][2] * s2, c[mt][nt][3] * s2);
        }
    }
}

// ---------------- GCN aggregation (fp16 in/out) + fused BN column stats ----------
__global__ __launch_bounds__(256)
void k_aggregate(const __half* __restrict__ hw, const float* __restrict__ bias,
                 __half* __restrict__ out, float* __restrict__ stats) {
    __shared__ float red[8][256];
    int d    = (blockIdx.x * blockDim.x + threadIdx.x) >> 5;
    int lane = threadIdx.x & 31;
    int wid  = threadIdx.x >> 5;

    float acc[8] = {};
    const int beg = g_off[d], end = g_off[d + 1];

    int p0 = beg;
    while (p0 < end) {
        int cnt = end - p0;
        if (cnt > 32) cnt = 32;
        int idxv = (lane < cnt) ? g_esrc[p0 + lane] : 0;
        int j = 0;
        for (; j + 4 <= cnt; j += 4) {
            int s0 = __shfl_sync(0xffffffffu, idxv, j);
            int s1 = __shfl_sync(0xffffffffu, idxv, j + 1);
            int s2 = __shfl_sync(0xffffffffu, idxv, j + 2);
            int s3 = __shfl_sync(0xffffffffu, idxv, j + 3);
            acc_edge(acc, hw, s0, lane);
            acc_edge(acc, hw, s1, lane);
            acc_edge(acc, hw, s2, lane);
            acc_edge(acc, hw, s3, lane);
        }
        for (; j < cnt; j++) {
            int s0 = __shfl_sync(0xffffffffu, idxv, j);
            acc_edge(acc, hw, s0, lane);
        }
        p0 += cnt;
    }

    float di = g_dinv[d];
    float sv[8], bv[8], r[8];
    ldh8(sv, hw + (size_t)d * HH, lane);
    ld8(bv, bias, lane);
    #pragma unroll
    for (int i = 0; i < 8; i++)
        r[i] = fmaxf(di * (acc[i] + sv[i]) + bv[i], 0.0f);
    sth8(out + (size_t)d * HH, lane, r);

    st8(&red[wid][0], lane, r);
    __syncthreads();
    int cidx = threadIdx.x;
    float s = 0.f, q = 0.f;
    #pragma unroll
    for (int w = 0; w < 8; w++) {
        float v = red[w][cidx];
        s += v; q += v * v;
    }
    atomicAdd(&stats[cidx], s);
    atomicAdd(&stats[256 + cidx], q);
}

// ---------------- BN -> LN -> fp16 store (layer 1) ----------------
__global__ __launch_bounds__(256)
void k_bn_ln1(const __half* __restrict__ t, const float* __restrict__ stats,
              const float* __restrict__ bng, const float* __restrict__ bnb,
              const float* __restrict__ lng, const float* __restrict__ lnb) {
    int row  = (blockIdx.x * blockDim.x + threadIdx.x) >> 5;
    int lane = threadIdx.x & 31;
    if (row >= NN) return;

    float v[8], s[8], q[8], g[8], b[8];
    ldh8(v, t + (size_t)row * HH, lane);
    ld8(s, stats, lane);
    ld8(q, stats + 256, lane);
    ld8(g, bng, lane);
    ld8(b, bnb, lane);

    #pragma unroll
    for (int i = 0; i < 8; i++) {
        float mu  = s[i] * (1.0f / NN);
        float var = q[i] * (1.0f / NN) - mu * mu;
        v[i] = g[i] * (v[i] - mu) * rsqrtf(var + 1e-5f) + b[i];
    }

    float sum = 0.f;
    #pragma unroll
    for (int i = 0; i < 8; i++) sum += v[i];
    #pragma unroll
    for (int o = 16; o; o >>= 1) sum += __shfl_xor_sync(0xffffffffu, sum, o);
    float mu = sum * (1.0f / HH);

    float ss = 0.f;
    #pragma unroll
    for (int i = 0; i < 8; i++) { float dd = v[i] - mu; ss += dd * dd; }
    #pragma unroll
    for (int o = 16; o; o >>= 1) ss += __shfl_xor_sync(0xffffffffu, ss, o);
    float rs = rsqrtf(ss * (1.0f / HH) + 1e-5f);

    ld8(g, lng, lane);
    ld8(b, lnb, lane);
    #pragma unroll
    for (int i = 0; i < 8; i++) v[i] = g[i] * (v[i] - mu) * rs + b[i];

    sth8(g_a2 + (size_t)row * HH, lane, v);
}

// ---------------- final: BN -> LN -> +residual(fp16) -> out-proj ----------------
__global__ __launch_bounds__(256)
void k_bn_ln_out(const __half* __restrict__ t, const float* __restrict__ stats,
                 const float* __restrict__ bng, const float* __restrict__ bnb,
                 const float* __restrict__ lng, const float* __restrict__ lnb,
                 const float* __restrict__ Wout, const float* __restrict__ bout,
                 float* __restrict__ out) {
    int row  = (blockIdx.x * blockDim.x + threadIdx.x) >> 5;
    int lane = threadIdx.x & 31;
    if (row >= NN) return;

    float v[8], s[8], q[8], g[8], b[8];
    ldh8(v, t + (size_t)row * HH, lane);
    ld8(s, stats, lane);
    ld8(q, stats + 256, lane);
    ld8(g, bng, lane);
    ld8(b, bnb, lane);

    #pragma unroll
    for (int i = 0; i < 8; i++) {
        float mu  = s[i] * (1.0f / NN);
        float var = q[i] * (1.0f / NN) - mu * mu;
        v[i] = g[i] * (v[i] - mu) * rsqrtf(var + 1e-5f) + b[i];
    }

    float sum = 0.f;
    #pragma unroll
    for (int i = 0; i < 8; i++) sum += v[i];
    #pragma unroll
    for (int o = 16; o; o >>= 1) sum += __shfl_xor_sync(0xffffffffu, sum, o);
    float mu = sum * (1.0f / HH);

    float ss = 0.f;
    #pragma unroll
    for (int i = 0; i < 8; i++) { float dd = v[i] - mu; ss += dd * dd; }
    #pragma unroll
    for (int o = 16; o; o >>= 1) ss += __shfl_xor_sync(0xffffffffu, ss, o);
    float rs = rsqrtf(ss * (1.0f / HH) + 1e-5f);

    ld8(g, lng, lane);
    ld8(b, lnb, lane);
    float r[8];
    ldh8(r, g_a2 + (size_t)row * HH, lane);
    #pragma unroll
    for (int i = 0; i < 8; i++) v[i] = g[i] * (v[i] - mu) * rs + b[i] + r[i];

    const float4* W4 = (const float4*)Wout;
    float4 wA = W4[2 * lane],      wB = W4[2 * lane + 1];
    float4 wC = W4[64 + 2 * lane], wD = W4[65 + 2 * lane];
    float a0 = v[0]*wA.x + v[1]*wA.z + v[2]*wB.x + v[3]*wB.z
             + v[4]*wC.x + v[5]*wC.z + v[6]*wD.x + v[7]*wD.z;
    float a1 = v[0]*wA.y + v[1]*wA.w + v[2]*wB.y + v[3]*wB.w
             + v[4]*wC.y + v[5]*wC.w + v[6]*wD.y + v[7]*wD.w;
    #pragma unroll
    for (int o = 16; o; o >>= 1) {
        a0 += __shfl_xor_sync(0xffffffffu, a0, o);
        a1 += __shfl_xor_sync(0xffffffffu, a1, o);
    }
    if (lane == 0) {
        out[2 * row]     = a0 + bout[0];
        out[2 * row + 1] = a1 + bout[1];
    }
}

// ---------------- streams + events ----------------
static cudaStream_t g_s2, g_s3;
static cudaEvent_t  g_evF, g_evZ, g_evD, g_evJ, g_evW;
namespace {
struct _HxInit {
    _HxInit() {
        cudaStreamCreateWithFlags(&g_s2, cudaStreamNonBlocking);
        cudaStreamCreateWithFlags(&g_s3, cudaStreamNonBlocking);
        cudaEventCreateWithFlags(&g_evF, cudaEventDisableTiming);
        cudaEventCreateWithFlags(&g_evZ, cudaEventDisableTiming);
        cudaEventCreateWithFlags(&g_evD, cudaEventDisableTiming);
        cudaEventCreateWithFlags(&g_evJ, cudaEventDisableTiming);
        cudaEventCreateWithFlags(&g_evW, cudaEventDisableTiming);
    }
};
static _HxInit _hx_init;
}

// ---------------- launch ----------------
extern "C" void kernel_launch(void* const* d_in, const int* in_sizes, int n_in,
                              void* d_out, int out_size) {
    const float* x    = (const float*)d_in[0];
    const int*   ei   = (const int*)  d_in[1];
    const float* fs   = (const float*)d_in[2];
    const float* fb   = (const float*)d_in[3];
    const float* bn0g = (const float*)d_in[4];
    const float* bn0b = (const float*)d_in[5];
    const float* W1   = (const float*)d_in[6];
    const float* b1   = (const float*)d_in[7];
    const float* bn1g = (const float*)d_in[8];
    const float* bn1b = (const float*)d_in[9];
    const float* ln1g = (const float*)d_in[10];
    const float* ln1b = (const float*)d_in[11];
    const float* W2   = (const float*)d_in[12];
    const float* b2   = (const float*)d_in[13];
    const float* bn2g = (const float*)d_in[14];
    const float* bn2b = (const float*)d_in[15];
    const float* ln2g = (const float*)d_in[16];
    const float* ln2b = (const float*)d_in[17];
    const float* Wout = (const float*)d_in[18];
    const float* bout = (const float*)d_in[19];
    float* out = (float*)d_out;

    const int* srcp = ei;
    const int* dstp = ei + EE;

    __half *p_hw, *p_h1, *p_h2, *p_a2, *p_w1, *p_w2;
    float *p_stats;
    cudaGetSymbolAddress((void**)&p_hw, g_hw);
    cudaGetSymbolAddress((void**)&p_h1, g_h1);
    cudaGetSymbolAddress((void**)&p_h2, g_h2);
    cudaGetSymbolAddress((void**)&p_a2, g_a2);
    cudaGetSymbolAddress((void**)&p_w1, g_w1);
    cudaGetSymbolAddress((void**)&p_w2, g_w2);
    cudaGetSymbolAddress((void**)&p_stats, g_stats);

    const int G1_SMEM = 2 * 128 * 136 * 2;        // 69632
    const int G2_SMEM = 2 * 2 * 128 * 72 * 2;     // 73728
    cudaFuncSetAttribute(k_gemm1, cudaFuncAttributeMaxDynamicSharedMemorySize, G1_SMEM);
    cudaFuncSetAttribute(k_gemm2, cudaFuncAttributeMaxDynamicSharedMemorySize, G2_SMEM);

    const int WARP_GRID = (NN * 32 + 255) / 256;  // 6250
    const dim3 MGRID(2, (NN + 127) / 128);

    // ---- fork ----
    cudaEventRecord(g_evF, 0);
    cudaStreamWaitEvent(g_s2, g_evF, 0);
    cudaStreamWaitEvent(g_s3, g_evF, 0);

    // side stream 2: stats zero + graph preprocessing
    k_zero_all<<<6, 256, 0, g_s2>>>();
    cudaEventRecord(g_evZ, g_s2);
    k_zero_deg<<<(NN + 255) / 256, 256, 0, g_s2>>>();
    k_count<<<(EE + 255) / 256, 256, 0, g_s2>>>(dstp);
    k_dinv<<<(NN + 255) / 256, 256, 0, g_s2>>>();
    cudaEventRecord(g_evD, g_s2);
    k_scan1<<<NBLK, 1024, 0, g_s2>>>();
    k_scan2<<<1, 64, 0, g_s2>>>();
    k_scan3<<<(NN + 1023) / 1024, 1024, 0, g_s2>>>();
    k_scatter<<<(EE + 255) / 256, 256, 0, g_s2>>>(srcp, dstp);
    cudaEventRecord(g_evJ, g_s2);

    // side stream 3: weight prep + BN0 stats/fold (inputs only + zeroed stats)
    k_prep_w<DIN><<<(HH * DIN + 255) / 256, 256, 0, g_s3>>>(W1, p_w1);
    k_prep_w<HH><<<(HH * HH + 255) / 256, 256, 0, g_s3>>>(W2, p_w2);
    cudaStreamWaitEvent(g_s3, g_evZ, 0);
    k_colstats0<<<1024, DIN, 0, g_s3>>>(x, fs, fb);
    k_folde<<<1, HH, 0, g_s3>>>(fs, fb, bn0g, bn0b, W1);
    cudaEventRecord(g_evW, g_s3);

    // ---- main stream: starts directly at GEMM1 ----
    cudaStreamWaitEvent(0, g_evD, 0);
    cudaStreamWaitEvent(0, g_evW, 0);
    k_gemm1<<<MGRID, 256, G1_SMEM>>>(x, p_w1, p_hw);
    cudaStreamWaitEvent(0, g_evJ, 0);
    k_aggregate<<<WARP_GRID, 256>>>(p_hw, b1, p_h1, p_stats + 512);
    k_bn_ln1<<<WARP_GRID, 256>>>(p_h1, p_stats + 512, bn1g, bn1b, ln1g, ln1b);

    // layer 2 (single-pass fp16 GEMM, residual from g_a2, fused out-proj)
    k_gemm2<<<MGRID, 256, G2_SMEM>>>(p_a2, p_w2, p_hw);
    k_aggregate<<<WARP_GRID, 256>>>(p_hw, b2, p_h2, p_stats + 1024);
    k_bn_ln_out<<<WARP_GRID, 256>>>(p_h2, p_stats + 1024,
                                    bn2g, bn2b, ln2g, ln2b,
                                    Wout, bout, out);
}